// round 11
// baseline (speedup 1.0000x reference)
#include <cuda_runtime.h>
#include <cuda_bf16.h>
#include <cstdint>

// Problem constants
#define BB 2
#define SS 2048
#define DD 1024
#define HH 16
#define HD 64
#define NEG (-1.0e9f)

// Scratch (device globals)
__device__ float g_q[BB * HH * SS * HD];     // [B,H,S,HD]  plain, tf32-rounded
__device__ float g_k[BB * HH * SS * HD];
__device__ float g_v[BB * HH * SS * HD];
__device__ float g_att[BB * SS * DD];        // [B,S,D] k-PERMUTED cols, tf32
__device__ float g_xc[BB * SS * DD];         // x, k-PERMUTED cols, tf32
__device__ float g_wq[DD * DD];              // W^T [n][k], k-PERMUTED, tf32
__device__ float g_wk[DD * DD];
__device__ float g_wv[DD * DD];
__device__ float g_wo[DD * DD];

// k-permutation within each 8-group: storage position of orig slot g is
// pos(g) = (g&3)*2 + (g>>2); inverse (orig slot at position p): INV[p]
__device__ __constant__ int c_inv[8] = {0, 4, 1, 5, 2, 6, 3, 7};

// ===========================================================================
// helpers
// ===========================================================================
__device__ __forceinline__ uint32_t f2tf32(float f) {
    uint32_t u;
    asm("cvt.rna.tf32.f32 %0, %1;" : "=r"(u) : "f"(f));
    return u;
}
__device__ __forceinline__ float f2tf32f(float f) {
    return __uint_as_float(f2tf32(f));
}

__device__ __forceinline__ uint32_t smem_u32(const void* p) {
    uint32_t a;
    asm("{ .reg .u64 t; cvta.to.shared.u64 t, %1; cvt.u32.u64 %0, t; }"
        : "=r"(a) : "l"(p));
    return a;
}

__device__ __forceinline__ void cp16(uint32_t dst, const void* src) {
    asm volatile("cp.async.ca.shared.global [%0], [%1], 16;"
                 :: "r"(dst), "l"(src));
}
#define CP_COMMIT() asm volatile("cp.async.commit_group;" ::: "memory")
#define CP_WAIT(N)  asm volatile("cp.async.wait_group %0;" :: "n"(N) : "memory")

__device__ __forceinline__ void mma_tf32(
    float* c, uint32_t a0, uint32_t a1, uint32_t a2, uint32_t a3,
    uint32_t b0, uint32_t b1)
{
    asm volatile(
        "mma.sync.aligned.m16n8k8.row.col.f32.tf32.tf32.f32 "
        "{%0,%1,%2,%3}, {%4,%5,%6,%7}, {%8,%9}, {%0,%1,%2,%3};"
        : "+f"(c[0]), "+f"(c[1]), "+f"(c[2]), "+f"(c[3])
        : "r"(a0), "r"(a1), "r"(a2), "r"(a3), "r"(b0), "r"(b1));
}

// ===========================================================================
// cvt_x: tf32-round x and permute columns within 8-groups.
// One thread per 8-float group: out = {f0,f4,f1,f5},{f2,f6,f3,f7}.
// ===========================================================================
#define XGRP (BB * SS * DD / 8)

__global__ __launch_bounds__(256) void cvt_x(const float* __restrict__ x)
{
    int g = blockIdx.x * blockDim.x + threadIdx.x;
    if (g >= XGRP) return;
    const float4* src = (const float4*)x + g * 2;
    float4 i0 = src[0], i1 = src[1];
    float4 o0, o1;
    o0.x = f2tf32f(i0.x); o0.y = f2tf32f(i1.x);
    o0.z = f2tf32f(i0.y); o0.w = f2tf32f(i1.y);
    o1.x = f2tf32f(i0.z); o1.y = f2tf32f(i1.z);
    o1.z = f2tf32f(i0.w); o1.w = f2tf32f(i1.w);
    float4* dst = (float4*)g_xc + g * 2;
    dst[0] = o0; dst[1] = o1;
}

// ===========================================================================
// cvt_w: transpose W [k][n] -> W^T [n][k], tf32-round, permute k within
// 8-groups. grid=(32,32,4), 256 threads, 32x32 tiles.
// ===========================================================================
__global__ __launch_bounds__(256) void cvt_w(
    const float* __restrict__ Wq, const float* __restrict__ Wk,
    const float* __restrict__ Wv, const float* __restrict__ Wo)
{
    __shared__ float t[32][33];
    const int z = blockIdx.z;
    const float* __restrict__ src = (z == 0) ? Wq : (z == 1) ? Wk
                                  : (z == 2) ? Wv : Wo;
    float* __restrict__ dst = (z == 0) ? g_wq : (z == 1) ? g_wk
                            : (z == 2) ? g_wv : g_wo;

    const int n0 = blockIdx.x * 32;
    const int k0 = blockIdx.y * 32;
    const int tid = threadIdx.x;
    const int tx = tid & 31, ty = tid >> 5;   // ty 0..7

#pragma unroll
    for (int j = 0; j < 4; j++)
        t[ty + j * 8][tx] = src[(size_t)(k0 + ty + j * 8) * DD + n0 + tx];
    __syncthreads();

    const int kq = tid & 7;      // output float4 group (0..7)
    const int row = tid >> 3;    // 0..31 (local n)
    const int kb = kq * 4;
    float4 o;
    o.x = f2tf32f(t[(kb + 0) & 24 ? c_inv[kb + 0] : c_inv[kb + 0]][row]);
    // (simple form below; above line kept trivial)
    o.x = f2tf32f(t[(kb & 24) + c_inv[(kb + 0) & 7]][row]);
    o.y = f2tf32f(t[(kb & 24) + c_inv[(kb + 1) & 7]][row]);
    o.z = f2tf32f(t[(kb & 24) + c_inv[(kb + 2) & 7]][row]);
    o.w = f2tf32f(t[(kb & 24) + c_inv[(kb + 3) & 7]][row]);
    *(float4*)&dst[(size_t)(n0 + row) * DD + k0 + kb] = o;
}

// ===========================================================================
// tf32 mma.sync GEMM: 128 threads = 4 warps (2m x 2n), warp tile 64x64,
// BK=32, 2-stage cp.async ring, LDS.64 fragment loads (k pre-permuted).
// Smem stride 40 (== 8 mod 32): conflict-free 64-bit loads.
// ===========================================================================
#define STR 40
#define TSZ (128 * STR)     // floats per (A or B) stage

__device__ __forceinline__ void gemm_issue(
    const float* __restrict__ A, const float* __restrict__ Wt,
    int m0, int n0, int c, uint32_t as_u, uint32_t bs_u, int tid)
{
#pragma unroll
    for (int i = 0; i < 8; i++) {
        int lin = i * 512 + tid * 4;
        int row = lin >> 5, col = lin & 31;
        uint32_t off = (uint32_t)(row * STR + col) * 4;
        cp16(as_u + off, A  + (size_t)(m0 + row) * DD + c * 32 + col);
        cp16(bs_u + off, Wt + (size_t)(n0 + row) * DD + c * 32 + col);
    }
}

__device__ __forceinline__ void tc_mainloop(
    const float* __restrict__ A, const float* __restrict__ Wt,
    int m0, int n0, float acc[4][8][4], float* AsG, float* BsG)
{
    const int tid = threadIdx.x;
    const int warp = tid >> 5, lane = tid & 31;
    const int wm0 = (warp & 1) * 64;
    const int wn0 = (warp >> 1) * 64;
    const int r = lane >> 2, cq = lane & 3;

    const uint32_t as_u = smem_u32(AsG);
    const uint32_t bs_u = smem_u32(BsG);

#pragma unroll
    for (int mi = 0; mi < 4; mi++)
#pragma unroll
        for (int ni = 0; ni < 8; ni++)
#pragma unroll
            for (int t = 0; t < 4; t++) acc[mi][ni][t] = 0.f;

    gemm_issue(A, Wt, m0, n0, 0, as_u, bs_u, tid); CP_COMMIT();

    for (int c = 0; c < 32; c++) {
        CP_WAIT(0);
        __syncthreads();

        if (c < 31) {
            int s = (c + 1) & 1;
            gemm_issue(A, Wt, m0, n0, c + 1,
                       as_u + (uint32_t)(s * TSZ) * 4,
                       bs_u + (uint32_t)(s * TSZ) * 4, tid);
            CP_COMMIT();
        }

        const uint32_t* Asu = (const uint32_t*)(AsG + (c & 1) * TSZ);
        const uint32_t* Bsu = (const uint32_t*)(BsG + (c & 1) * TSZ);
#pragma unroll
        for (int ks = 0; ks < 4; ks++) {
            const int k8 = ks * 8 + 2 * cq;
            uint2 alo[4], ahi[4], bb[8];
#pragma unroll
            for (int mi = 0; mi < 4; mi++) {
                int mb = wm0 + mi * 16;
                alo[mi] = *(const uint2*)&Asu[(mb + r) * STR + k8];      // (a0,a2)
                ahi[mi] = *(const uint2*)&Asu[(mb + r + 8) * STR + k8];  // (a1,a3)
            }
#pragma unroll
            for (int ni = 0; ni < 8; ni++)
                bb[ni] = *(const uint2*)&Bsu[(wn0 + ni * 8 + r) * STR + k8]; // (b0,b1)
#pragma unroll
            for (int mi = 0; mi < 4; mi++)
#pragma unroll
                for (int ni = 0; ni < 8; ni++)
                    mma_tf32(acc[mi][ni], alo[mi].x, ahi[mi].x, alo[mi].y, ahi[mi].y,
                             bb[ni].x, bb[ni].y);
        }
    }
}

// ---------------------------------------------------------------------------
// QKV projection. grid=(8, 32, 3), 128 threads. Stores PLAIN tf32 Q/K/V.
// ---------------------------------------------------------------------------
__global__ __launch_bounds__(128, 2) void qkv_mma(
    const float* __restrict__ bq, const float* __restrict__ bk,
    const float* __restrict__ bv)
{
    extern __shared__ float dsm[];
    float* AsG = dsm;
    float* BsG = dsm + 2 * TSZ;

    const int z = blockIdx.z;
    const float* __restrict__ Wt = (z == 0) ? g_wq : (z == 1) ? g_wk : g_wv;
    const float* __restrict__ bias = (z == 0) ? bq : (z == 1) ? bk : bv;
    float* __restrict__ out = (z == 0) ? g_q : (z == 1) ? g_k : g_v;

    const int m0 = blockIdx.y * 128;
    const int n0 = blockIdx.x * 128;

    float acc[4][8][4];
    tc_mainloop(g_xc, Wt, m0, n0, acc, AsG, BsG);

    const int tid = threadIdx.x;
    const int warp = tid >> 5, lane = tid & 31;
    const int wm0 = (warp & 1) * 64;
    const int wn0 = (warp >> 1) * 64;
    const int r = lane >> 2, cq = lane & 3;

#pragma unroll
    for (int mi = 0; mi < 4; mi++) {
#pragma unroll
        for (int ni = 0; ni < 8; ni++) {
            int ncol = n0 + wn0 + ni * 8 + 2 * cq;
            int h = ncol >> 6, d = ncol & 63;
            float b0v = bias[ncol], b1v = bias[ncol + 1];
#pragma unroll
            for (int half = 0; half < 2; half++) {
                int mrow = m0 + wm0 + mi * 16 + r + half * 8;
                int bidx = mrow >> 11, s = mrow & (SS - 1);
                float2 o;
                o.x = f2tf32f(acc[mi][ni][half * 2 + 0] + b0v);
                o.y = f2tf32f(acc[mi][ni][half * 2 + 1] + b1v);
                *(float2*)(out + (size_t)((bidx * HH + h) * SS + s) * HD + d) = o;
            }
        }
    }
}

// ---------------------------------------------------------------------------
// Output projection. grid=(8, 32), 128 threads. A = g_att (k-permuted).
// ---------------------------------------------------------------------------
__global__ __launch_bounds__(128, 2) void oproj_mma(
    const float* __restrict__ bo, float* __restrict__ out)
{
    extern __shared__ float dsm[];
    float* AsG = dsm;
    float* BsG = dsm + 2 * TSZ;

    const int m0 = blockIdx.y * 128;
    const int n0 = blockIdx.x * 128;

    float acc[4][8][4];
    tc_mainloop(g_att, g_wo, m0, n0, acc, AsG, BsG);

    const int tid = threadIdx.x;
    const int warp = tid >> 5, lane = tid & 31;
    const int wm0 = (warp & 1) * 64;
    const int wn0 = (warp >> 1) * 64;
    const int r = lane >> 2, cq = lane & 3;

#pragma unroll
    for (int mi = 0; mi < 4; mi++) {
#pragma unroll
        for (int ni = 0; ni < 8; ni++) {
            int ncol = n0 + wn0 + ni * 8 + 2 * cq;
            float b0v = bo[ncol], b1v = bo[ncol + 1];
#pragma unroll
            for (int half = 0; half < 2; half++) {
                int mrow = m0 + wm0 + mi * 16 + r + half * 8;
                float2 o;
                o.x = acc[mi][ni][half * 2 + 0] + b0v;
                o.y = acc[mi][ni][half * 2 + 1] + b1v;
                *(float2*)(out + (size_t)mrow * DD + ncol) = o;
            }
        }
    }
}

// ===========================================================================
// Flash attention (unchanged mainloop from R10). Epilogue writes g_att with
// k-permuted columns (two scalar stores per pair).
// ===========================================================================
#define SA 68
#define QR 256
#define KVSTG (2 * 64 * SA)

__global__ __launch_bounds__(256, 1) void attn_mma(const float* __restrict__ mask)
{
    extern __shared__ float smf[];
    float* Qs = smf;                      // [256][SA]
    float* KV = Qs + QR * SA;             // 3 stages x (K[64*SA] + V[64*SA])
    float* Ms = KV + 3 * KVSTG;           // [2048] additive mask row

    const uint32_t* Qu = (const uint32_t*)Qs;
    const uint32_t qs_u = smem_u32(Qs);
    const uint32_t kv_u = smem_u32(KV);

    const int qt = gridDim.x - 1 - blockIdx.x;   // big tiles first
    const int h = blockIdx.y, b = blockIdx.z;
    const int tid = threadIdx.x, warp = tid >> 5, lane = tid & 31;
    const int r = lane >> 2, cq = lane & 3;
    const int wm = warp * 32;
    const int q0 = qt * QR;

    const float* kroot = g_k + (size_t)((b * HH + h) * SS) * HD;
    const float* vroot = g_v + (size_t)((b * HH + h) * SS) * HD;

    const float* qbase = g_q + (size_t)((b * HH + h) * SS + q0) * HD;
#pragma unroll
    for (int p = 0; p < 16; p++) {
        int lin = p * 1024 + tid * 4;
        int rr = lin >> 6, dd = lin & 63;
        cp16(qs_u + (uint32_t)(rr * SA + dd) * 4, qbase + rr * 64 + dd);
    }
    CP_COMMIT();

    auto issue_kv = [&](int jt) {
        int st = jt % 3;
        uint32_t ku = kv_u + (uint32_t)(st * KVSTG) * 4;
        uint32_t vu = ku + (uint32_t)(64 * SA) * 4;
        const float* kb = kroot + (size_t)(jt * 64) * HD;
        const float* vb = vroot + (size_t)(jt * 64) * HD;
#pragma unroll
        for (int p = 0; p < 4; p++) {
            int lin = p * 1024 + tid * 4;
            int rr = lin >> 6, dd = lin & 63;
            uint32_t off = (uint32_t)(rr * SA + dd) * 4;
            cp16(ku + off, kb + rr * 64 + dd);
            cp16(vu + off, vb + rr * 64 + dd);
        }
    };

    issue_kv(0); CP_COMMIT();
    issue_kv(1); CP_COMMIT();

#pragma unroll
    for (int p = 0; p < 8; p++) {
        int idx = p * 256 + tid;
        Ms[idx] = (1.f - mask[b * SS + idx]) * NEG;
    }

    float o[2][8][4];
#pragma unroll
    for (int mi = 0; mi < 2; mi++)
#pragma unroll
        for (int ni = 0; ni < 8; ni++)
#pragma unroll
            for (int t = 0; t < 4; t++) o[mi][ni][t] = 0.f;
    float mst[2][2] = {{-1e30f, -1e30f}, {-1e30f, -1e30f}};
    float lst[2][2] = {{0.f, 0.f}, {0.f, 0.f}};

    const int jt_max = 4 * qt + 3;
    const int rowbase = q0 + wm;
    const int src0 = (lane & ~3) | (cq >> 1);
    const int src1 = src0 + 2;
    const bool oddl = cq & 1;

    for (int jt = 0; jt <= jt_max; jt++) {
        CP_WAIT(1);
        __syncthreads();

        if (jt + 2 <= jt_max) issue_kv(jt + 2);
        CP_COMMIT();

        const uint32_t* Ku = (const uint32_t*)(KV + (jt % 3) * KVSTG);
        const uint32_t* Vu = Ku + 64 * SA;
        const float* madd = Ms + jt * 64;

        float s[2][8][4];
#pragma unroll
        for (int mi = 0; mi < 2; mi++)
#pragma unroll
            for (int ni = 0; ni < 8; ni++)
#pragma unroll
                for (int t = 0; t < 4; t++) s[mi][ni][t] = 0.f;
#pragma unroll
        for (int ks = 0; ks < 8; ks++) {
            const int k = ks * 8;
            uint32_t a0[2], a1[2], a2[2], a3[2];
#pragma unroll
            for (int mi = 0; mi < 2; mi++) {
                int mb = wm + mi * 16;
                a0[mi] = Qu[(mb + r) * SA + k + cq];
                a1[mi] = Qu[(mb + r + 8) * SA + k + cq];
                a2[mi] = Qu[(mb + r) * SA + k + cq + 4];
                a3[mi] = Qu[(mb + r + 8) * SA + k + cq + 4];
            }
#pragma unroll
            for (int ni = 0; ni < 8; ni++) {
                uint32_t b0 = Ku[(8 * ni + r) * SA + k + cq];
                uint32_t b1 = Ku[(8 * ni + r) * SA + k + cq + 4];
                mma_tf32(s[0][ni], a0[0], a1[0], a2[0], a3[0], b0, b1);
                mma_tf32(s[1][ni], a0[1], a1[1], a2[1], a3[1], b0, b1);
            }
        }

        const bool part = (jt * 64 + 63 > rowbase);
        const int colb = jt * 64;
#pragma unroll
        for (int mi = 0; mi < 2; mi++) {
#pragma unroll
            for (int ni = 0; ni < 8; ni++) {
#pragma unroll
                for (int t = 0; t < 4; t++) {
                    int col = 8 * ni + 2 * cq + (t & 1);
                    int rowg = rowbase + mi * 16 + r + ((t < 2) ? 0 : 8);
                    float v;
                    if (part && (colb + col > rowg)) v = NEG + madd[col];
                    else                             v = s[mi][ni][t] * 0.125f + madd[col];
                    s[mi][ni][t] = v;
                }
            }
        }

#pragma unroll
        for (int mi = 0; mi < 2; mi++) {
            float mx0 = -1e30f, mx1 = -1e30f;
#pragma unroll
            for (int ni = 0; ni < 8; ni++) {
                mx0 = fmaxf(mx0, fmaxf(s[mi][ni][0], s[mi][ni][1]));
                mx1 = fmaxf(mx1, fmaxf(s[mi][ni][2], s[mi][ni][3]));
            }
            mx0 = fmaxf(mx0, __shfl_xor_sync(0xffffffff, mx0, 1));
            mx0 = fmaxf(mx0, __shfl_xor_sync(0xffffffff, mx0, 2));
            mx1 = fmaxf(mx1, __shfl_xor_sync(0xffffffff, mx1, 1));
            mx1 = fmaxf(mx1, __shfl_xor_sync(0xffffffff, mx1, 2));

            float nm0 = fmaxf(mst[mi][0], mx0), nm1 = fmaxf(mst[mi][1], mx1);
            float sc0 = __expf(mst[mi][0] - nm0), sc1 = __expf(mst[mi][1] - nm1);
            float sum0 = 0.f, sum1 = 0.f;
#pragma unroll
            for (int ni = 0; ni < 8; ni++) {
                s[mi][ni][0] = __expf(s[mi][ni][0] - nm0);
                s[mi][ni][1] = __expf(s[mi][ni][1] - nm0);
                s[mi][ni][2] = __expf(s[mi][ni][2] - nm1);
                s[mi][ni][3] = __expf(s[mi][ni][3] - nm1);
                sum0 += s[mi][ni][0] + s[mi][ni][1];
                sum1 += s[mi][ni][2] + s[mi][ni][3];
            }
            sum0 += __shfl_xor_sync(0xffffffff, sum0, 1);
            sum0 += __shfl_xor_sync(0xffffffff, sum0, 2);
            sum1 += __shfl_xor_sync(0xffffffff, sum1, 1);
            sum1 += __shfl_xor_sync(0xffffffff, sum1, 2);

            lst[mi][0] = lst[mi][0] * sc0 + sum0;  mst[mi][0] = nm0;
            lst[mi][1] = lst[mi][1] * sc1 + sum1;  mst[mi][1] = nm1;

#pragma unroll
            for (int ni = 0; ni < 8; ni++) {
                o[mi][ni][0] *= sc0; o[mi][ni][1] *= sc0;
                o[mi][ni][2] *= sc1; o[mi][ni][3] *= sc1;
            }
        }

#pragma unroll
        for (int ks = 0; ks < 8; ks++) {
            uint32_t pa0[2], pa1[2], pa2[2], pa3[2];
#pragma unroll
            for (int mi = 0; mi < 2; mi++) {
                uint32_t q0r = f2tf32(s[mi][ks][0]), q1r = f2tf32(s[mi][ks][1]);
                uint32_t q2r = f2tf32(s[mi][ks][2]), q3r = f2tf32(s[mi][ks][3]);
                uint32_t x00 = __shfl_sync(0xffffffff, q0r, src0);
                uint32_t x01 = __shfl_sync(0xffffffff, q1r, src0);
                uint32_t x10 = __shfl_sync(0xffffffff, q2r, src0);
                uint32_t x11 = __shfl_sync(0xffffffff, q3r, src0);
                uint32_t x20 = __shfl_sync(0xffffffff, q0r, src1);
                uint32_t x21 = __shfl_sync(0xffffffff, q1r, src1);
                uint32_t x30 = __shfl_sync(0xffffffff, q2r, src1);
                uint32_t x31 = __shfl_sync(0xffffffff, q3r, src1);
                pa0[mi] = oddl ? x01 : x00;
                pa1[mi] = oddl ? x11 : x10;
                pa2[mi] = oddl ? x21 : x20;
                pa3[mi] = oddl ? x31 : x30;
            }
            const int k = ks * 8;
#pragma unroll
            for (int ni = 0; ni < 8; ni++) {
                uint32_t b0 = Vu[(k + cq) * SA + 8 * ni + r];
                uint32_t b1 = Vu[(k + cq + 4) * SA + 8 * ni + r];
                mma_tf32(o[0][ni], pa0[0], pa1[0], pa2[0], pa3[0], b0, b1);
                mma_tf32(o[1][ni], pa0[1], pa1[1], pa2[1], pa3[1], b0, b1);
            }
        }
    }

    // ---- epilogue: normalize, tf32-round, write PERMUTED g_att columns.
    // orig cols (2cq, 2cq+1) within the 8-group -> positions posE, posO.
    const int gE = 2 * cq, gO = 2 * cq + 1;
    const int posE = (gE & 3) * 2 + (gE >> 2);
    const int posO = (gO & 3) * 2 + (gO >> 2);
#pragma unroll
    for (int mi = 0; mi < 2; mi++) {
        float inv0 = 1.f / lst[mi][0], inv1 = 1.f / lst[mi][1];
        int rw0 = rowbase + mi * 16 + r;
        float* ob0 = g_att + (size_t)(b * SS + rw0) * DD + h * HD;
        float* ob1 = g_att + (size_t)(b * SS + rw0 + 8) * DD + h * HD;
#pragma unroll
        for (int ni = 0; ni < 8; ni++) {
            int gbase = 8 * ni;   // group base within head (8-aligned)
            ob0[gbase + posE] = f2tf32f(o[mi][ni][0] * inv0);
            ob0[gbase + posO] = f2tf32f(o[mi][ni][1] * inv0);
            ob1[gbase + posE] = f2tf32f(o[mi][ni][2] * inv1);
            ob1[gbase + posO] = f2tf32f(o[mi][ni][3] * inv1);
        }
    }
}

// ---------------------------------------------------------------------------
extern "C" void kernel_launch(void* const* d_in, const int* in_sizes, int n_in,
                              void* d_out, int out_size)
{
    const float* x    = (const float*)d_in[0];
    const float* mask = (const float*)d_in[1];
    const float* Wq   = (const float*)d_in[2];
    const float* bq   = (const float*)d_in[3];
    const float* Wk   = (const float*)d_in[4];
    const float* bk   = (const float*)d_in[5];
    const float* Wv   = (const float*)d_in[6];
    const float* bv   = (const float*)d_in[7];
    const float* Wo   = (const float*)d_in[8];
    const float* bo   = (const float*)d_in[9];
    float* out = (float*)d_out;

    cvt_x<<<(XGRP + 255) / 256, 256>>>(x);
    dim3 gw(32, 32, 4);
    cvt_w<<<gw, 256>>>(Wq, Wk, Wv, Wo);

    const int gemm_smem = 2 * 2 * TSZ * sizeof(float);                    // 80 KB
    const int attn_smem = (QR * SA + 3 * KVSTG + SS) * sizeof(float);     // ~182.3 KB
    cudaFuncSetAttribute(qkv_mma,   cudaFuncAttributeMaxDynamicSharedMemorySize, gemm_smem);
    cudaFuncSetAttribute(oproj_mma, cudaFuncAttributeMaxDynamicSharedMemorySize, gemm_smem);
    cudaFuncSetAttribute(attn_mma,  cudaFuncAttributeMaxDynamicSharedMemorySize, attn_smem);

    dim3 gq(DD / 128, (BB * SS) / 128, 3);
    qkv_mma<<<gq, 128, gemm_smem>>>(bq, bk, bv);

    dim3 ga(SS / QR, HH, BB);
    attn_mma<<<ga, 256, attn_smem>>>(mask);

    dim3 go(DD / 128, (BB * SS) / 128);
    oproj_mma<<<go, 128, gemm_smem>>>(bo, out);
}

// round 12
// speedup vs baseline: 1.4353x; 1.4353x over previous
#include <cuda_runtime.h>
#include <cuda_bf16.h>
#include <cstdint>

// Problem constants
#define BB 2
#define SS 2048
#define DD 1024
#define HH 16
#define HD 64
#define NEG (-1.0e9f)

// Scratch (device globals)
__device__ float g_q[BB * HH * SS * HD];     // [B,H,S,HD]  plain, tf32-rounded
__device__ float g_k[BB * HH * SS * HD];
__device__ float g_v[BB * HH * SS * HD];
__device__ float g_att[BB * SS * DD];        // [B,S,D] plain, tf32-rounded
__device__ float g_xc[BB * SS * DD];         // x, plain, tf32-rounded
__device__ float g_wq[DD * DD];              // W^T [n][k], k-permuted, tf32
__device__ float g_wk[DD * DD];
__device__ float g_wv[DD * DD];
__device__ float g_wo[DD * DD];

// storage position p holds original k-slot INV[p] within each 8-group
__device__ __constant__ int c_inv[8] = {0, 4, 1, 5, 2, 6, 3, 7};

// ===========================================================================
// helpers
// ===========================================================================
__device__ __forceinline__ uint32_t f2tf32(float f) {
    uint32_t u;
    asm("cvt.rna.tf32.f32 %0, %1;" : "=r"(u) : "f"(f));
    return u;
}
__device__ __forceinline__ float f2tf32f(float f) {
    return __uint_as_float(f2tf32(f));
}

__device__ __forceinline__ uint32_t smem_u32(const void* p) {
    uint32_t a;
    asm("{ .reg .u64 t; cvta.to.shared.u64 t, %1; cvt.u32.u64 %0, t; }"
        : "=r"(a) : "l"(p));
    return a;
}

__device__ __forceinline__ void cp16(uint32_t dst, const void* src) {
    asm volatile("cp.async.ca.shared.global [%0], [%1], 16;"
                 :: "r"(dst), "l"(src));
}
#define CP_COMMIT() asm volatile("cp.async.commit_group;" ::: "memory")
#define CP_WAIT(N)  asm volatile("cp.async.wait_group %0;" :: "n"(N) : "memory")

__device__ __forceinline__ void mma_tf32(
    float* c, uint32_t a0, uint32_t a1, uint32_t a2, uint32_t a3,
    uint32_t b0, uint32_t b1)
{
    asm volatile(
        "mma.sync.aligned.m16n8k8.row.col.f32.tf32.tf32.f32 "
        "{%0,%1,%2,%3}, {%4,%5,%6,%7}, {%8,%9}, {%0,%1,%2,%3};"
        : "+f"(c[0]), "+f"(c[1]), "+f"(c[2]), "+f"(c[3])
        : "r"(a0), "r"(a1), "r"(a2), "r"(a3), "r"(b0), "r"(b1));
}

// ===========================================================================
// cvt_x: tf32-round x (plain layout)
// ===========================================================================
#define X4 (BB * SS * DD / 4)

__global__ __launch_bounds__(256) void cvt_x(const float* __restrict__ x)
{
    int i = blockIdx.x * blockDim.x + threadIdx.x;
    if (i >= X4) return;
    float4 v = ((const float4*)x)[i];
    float4 q;
    q.x = f2tf32f(v.x); q.y = f2tf32f(v.y);
    q.z = f2tf32f(v.z); q.w = f2tf32f(v.w);
    ((float4*)g_xc)[i] = q;
}

// ===========================================================================
// cvt_w: W [k][n] -> W^T [n][k] with per-8-group k permutation, tf32-round.
// grid=(32,32,4), 256 threads, 32x32 tiles.
// ===========================================================================
__global__ __launch_bounds__(256) void cvt_w(
    const float* __restrict__ Wq, const float* __restrict__ Wk,
    const float* __restrict__ Wv, const float* __restrict__ Wo)
{
    __shared__ float t[32][33];
    const int z = blockIdx.z;
    const float* __restrict__ src = (z == 0) ? Wq : (z == 1) ? Wk
                                  : (z == 2) ? Wv : Wo;
    float* __restrict__ dst = (z == 0) ? g_wq : (z == 1) ? g_wk
                            : (z == 2) ? g_wv : g_wo;

    const int n0 = blockIdx.x * 32;
    const int k0 = blockIdx.y * 32;
    const int tid = threadIdx.x;
    const int tx = tid & 31, ty = tid >> 5;

#pragma unroll
    for (int j = 0; j < 4; j++)
        t[ty + j * 8][tx] = src[(size_t)(k0 + ty + j * 8) * DD + n0 + tx];
    __syncthreads();

    const int kq = tid & 7;      // output float4 group
    const int row = tid >> 3;    // local n 0..31
    const int kb = kq * 4;
    float4 o;
    o.x = f2tf32f(t[(kb & 24) + c_inv[(kb + 0) & 7]][row]);
    o.y = f2tf32f(t[(kb & 24) + c_inv[(kb + 1) & 7]][row]);
    o.z = f2tf32f(t[(kb & 24) + c_inv[(kb + 2) & 7]][row]);
    o.w = f2tf32f(t[(kb & 24) + c_inv[(kb + 3) & 7]][row]);
    *(float4*)&dst[(size_t)(n0 + row) * DD + k0 + kb] = o;
}

// ===========================================================================
// tf32 mma.sync GEMM: 128 threads = 4 warps (2m x 2n), warp tile 64x64,
// BK=32, 3-stage cp.async ring (R10 structure).
// A: [m][k] stride 36, plain k (LDS.32 fragments, R10-identical).
// B: Wt [n][k] k-permuted, packed stride 32 + XOR swizzle -> LDS.64 frags.
// ===========================================================================
#define STRA 36
#define ASTG (128 * STRA)    // 4608 floats
#define BSTG (128 * 32)      // 4096 floats

__device__ __forceinline__ void gemm_issue(
    const float* __restrict__ A, const float* __restrict__ Wt,
    int m0, int n0, int c, uint32_t as_u, uint32_t bs_u, int tid)
{
#pragma unroll
    for (int i = 0; i < 8; i++) {
        int lin = i * 512 + tid * 4;
        int row = lin >> 5, col = lin & 31;
        cp16(as_u + (uint32_t)(row * STRA + col) * 4,
             A + (size_t)(m0 + row) * DD + c * 32 + col);
        int swc = col ^ ((row & 3) << 3);
        cp16(bs_u + (uint32_t)(row * 32 + swc) * 4,
             Wt + (size_t)(n0 + row) * DD + c * 32 + col);
    }
}

__device__ __forceinline__ void tc_mainloop(
    const float* __restrict__ A, const float* __restrict__ Wt,
    int m0, int n0, float acc[4][8][4], float* AsG, float* BsG)
{
    const int tid = threadIdx.x;
    const int warp = tid >> 5, lane = tid & 31;
    const int wm0 = (warp & 1) * 64;
    const int wn0 = (warp >> 1) * 64;
    const int r = lane >> 2, cq = lane & 3;
    const int rsw = (r & 3) << 3;

    const uint32_t as_u = smem_u32(AsG);
    const uint32_t bs_u = smem_u32(BsG);

#pragma unroll
    for (int mi = 0; mi < 4; mi++)
#pragma unroll
        for (int ni = 0; ni < 8; ni++)
#pragma unroll
            for (int t = 0; t < 4; t++) acc[mi][ni][t] = 0.f;

    gemm_issue(A, Wt, m0, n0, 0, as_u, bs_u, tid); CP_COMMIT();
    gemm_issue(A, Wt, m0, n0, 1, as_u + ASTG * 4, bs_u + BSTG * 4, tid); CP_COMMIT();

    for (int c = 0; c < 32; c++) {
        CP_WAIT(1);
        __syncthreads();

        if (c < 30) {
            int s = (c + 2) % 3;
            gemm_issue(A, Wt, m0, n0, c + 2,
                       as_u + (uint32_t)(s * ASTG) * 4,
                       bs_u + (uint32_t)(s * BSTG) * 4, tid);
        }
        CP_COMMIT();

        const uint32_t* Asu = (const uint32_t*)(AsG + (c % 3) * ASTG);
        const uint32_t* Bsu = (const uint32_t*)(BsG + (c % 3) * BSTG);
#pragma unroll
        for (int ks = 0; ks < 4; ks++) {
            const int k = ks * 8;
            const int swb = (k + 2 * cq) ^ rsw;
            uint32_t af[4][4];
            uint2 bb[8];
#pragma unroll
            for (int mi = 0; mi < 4; mi++) {
                int mb = wm0 + mi * 16;
                af[mi][0] = Asu[(mb + r) * STRA + k + cq];
                af[mi][1] = Asu[(mb + r + 8) * STRA + k + cq];
                af[mi][2] = Asu[(mb + r) * STRA + k + cq + 4];
                af[mi][3] = Asu[(mb + r + 8) * STRA + k + cq + 4];
            }
#pragma unroll
            for (int ni = 0; ni < 8; ni++)
                bb[ni] = *(const uint2*)&Bsu[(wn0 + ni * 8 + r) * 32 + swb];
#pragma unroll
            for (int mi = 0; mi < 4; mi++)
#pragma unroll
                for (int ni = 0; ni < 8; ni++)
                    mma_tf32(acc[mi][ni], af[mi][0], af[mi][1], af[mi][2], af[mi][3],
                             bb[ni].x, bb[ni].y);
        }
    }
}

// ---------------------------------------------------------------------------
// QKV projection. grid=(8, 32, 3), 128 threads. Stores plain tf32 Q/K/V.
// ---------------------------------------------------------------------------
__global__ __launch_bounds__(128, 2) void qkv_mma(
    const float* __restrict__ bq, const float* __restrict__ bk,
    const float* __restrict__ bv)
{
    extern __shared__ float dsm[];
    float* AsG = dsm;
    float* BsG = dsm + 3 * ASTG;

    const int z = blockIdx.z;
    const float* __restrict__ Wt = (z == 0) ? g_wq : (z == 1) ? g_wk : g_wv;
    const float* __restrict__ bias = (z == 0) ? bq : (z == 1) ? bk : bv;
    float* __restrict__ out = (z == 0) ? g_q : (z == 1) ? g_k : g_v;

    const int m0 = blockIdx.y * 128;
    const int n0 = blockIdx.x * 128;

    float acc[4][8][4];
    tc_mainloop(g_xc, Wt, m0, n0, acc, AsG, BsG);

    const int tid = threadIdx.x;
    const int warp = tid >> 5, lane = tid & 31;
    const int wm0 = (warp & 1) * 64;
    const int wn0 = (warp >> 1) * 64;
    const int r = lane >> 2, cq = lane & 3;

#pragma unroll
    for (int mi = 0; mi < 4; mi++) {
#pragma unroll
        for (int ni = 0; ni < 8; ni++) {
            int ncol = n0 + wn0 + ni * 8 + 2 * cq;
            int h = ncol >> 6, d = ncol & 63;
            float b0v = bias[ncol], b1v = bias[ncol + 1];
#pragma unroll
            for (int half = 0; half < 2; half++) {
                int mrow = m0 + wm0 + mi * 16 + r + half * 8;
                int bidx = mrow >> 11, s = mrow & (SS - 1);
                float2 o;
                o.x = f2tf32f(acc[mi][ni][half * 2 + 0] + b0v);
                o.y = f2tf32f(acc[mi][ni][half * 2 + 1] + b1v);
                *(float2*)(out + (size_t)((bidx * HH + h) * SS + s) * HD + d) = o;
            }
        }
    }
}

// ---------------------------------------------------------------------------
// Output projection. grid=(8, 32), 128 threads.
// ---------------------------------------------------------------------------
__global__ __launch_bounds__(128, 2) void oproj_mma(
    const float* __restrict__ bo, float* __restrict__ out)
{
    extern __shared__ float dsm[];
    float* AsG = dsm;
    float* BsG = dsm + 3 * ASTG;

    const int m0 = blockIdx.y * 128;
    const int n0 = blockIdx.x * 128;

    float acc[4][8][4];
    tc_mainloop(g_att, g_wo, m0, n0, acc, AsG, BsG);

    const int tid = threadIdx.x;
    const int warp = tid >> 5, lane = tid & 31;
    const int wm0 = (warp & 1) * 64;
    const int wn0 = (warp >> 1) * 64;
    const int r = lane >> 2, cq = lane & 3;

#pragma unroll
    for (int mi = 0; mi < 4; mi++) {
#pragma unroll
        for (int ni = 0; ni < 8; ni++) {
            int ncol = n0 + wn0 + ni * 8 + 2 * cq;
            float b0v = bo[ncol], b1v = bo[ncol + 1];
#pragma unroll
            for (int half = 0; half < 2; half++) {
                int mrow = m0 + wm0 + mi * 16 + r + half * 8;
                float2 o;
                o.x = acc[mi][ni][half * 2 + 0] + b0v;
                o.y = acc[mi][ni][half * 2 + 1] + b1v;
                *(float2*)(out + (size_t)mrow * DD + ncol) = o;
            }
        }
    }
}

// ===========================================================================
// Flash attention, tf32 mma.sync. (EXACT R10 kernel)
// 256 q-rows/block, 256 threads = 8 warps, 32 q-rows per warp (2 m-tiles).
// 3-stage cp.async KV ring -> ONE __syncthreads per tile; mask preloaded.
// ===========================================================================
#define SA 68
#define QR 256
#define KVSTG (2 * 64 * SA)

__global__ __launch_bounds__(256, 1) void attn_mma(const float* __restrict__ mask)
{
    extern __shared__ float smf[];
    float* Qs = smf;                      // [256][SA]
    float* KV = Qs + QR * SA;             // 3 stages x (K[64*SA] + V[64*SA])
    float* Ms = KV + 3 * KVSTG;           // [2048] additive mask row

    const uint32_t* Qu = (const uint32_t*)Qs;
    const uint32_t qs_u = smem_u32(Qs);
    const uint32_t kv_u = smem_u32(KV);

    const int qt = gridDim.x - 1 - blockIdx.x;   // big tiles first
    const int h = blockIdx.y, b = blockIdx.z;
    const int tid = threadIdx.x, warp = tid >> 5, lane = tid & 31;
    const int r = lane >> 2, cq = lane & 3;
    const int wm = warp * 32;
    const int q0 = qt * QR;

    const float* kroot = g_k + (size_t)((b * HH + h) * SS) * HD;
    const float* vroot = g_v + (size_t)((b * HH + h) * SS) * HD;

    const float* qbase = g_q + (size_t)((b * HH + h) * SS + q0) * HD;
#pragma unroll
    for (int p = 0; p < 16; p++) {
        int lin = p * 1024 + tid * 4;
        int rr = lin >> 6, dd = lin & 63;
        cp16(qs_u + (uint32_t)(rr * SA + dd) * 4, qbase + rr * 64 + dd);
    }
    CP_COMMIT();

    auto issue_kv = [&](int jt) {
        int st = jt % 3;
        uint32_t ku = kv_u + (uint32_t)(st * KVSTG) * 4;
        uint32_t vu = ku + (uint32_t)(64 * SA) * 4;
        const float* kb = kroot + (size_t)(jt * 64) * HD;
        const float* vb = vroot + (size_t)(jt * 64) * HD;
#pragma unroll
        for (int p = 0; p < 4; p++) {
            int lin = p * 1024 + tid * 4;
            int rr = lin >> 6, dd = lin & 63;
            uint32_t off = (uint32_t)(rr * SA + dd) * 4;
            cp16(ku + off, kb + rr * 64 + dd);
            cp16(vu + off, vb + rr * 64 + dd);
        }
    };

    issue_kv(0); CP_COMMIT();
    issue_kv(1); CP_COMMIT();

#pragma unroll
    for (int p = 0; p < 8; p++) {
        int idx = p * 256 + tid;
        Ms[idx] = (1.f - mask[b * SS + idx]) * NEG;
    }

    float o[2][8][4];
#pragma unroll
    for (int mi = 0; mi < 2; mi++)
#pragma unroll
        for (int ni = 0; ni < 8; ni++)
#pragma unroll
            for (int t = 0; t < 4; t++) o[mi][ni][t] = 0.f;
    float mst[2][2] = {{-1e30f, -1e30f}, {-1e30f, -1e30f}};
    float lst[2][2] = {{0.f, 0.f}, {0.f, 0.f}};

    const int jt_max = 4 * qt + 3;
    const int rowbase = q0 + wm;
    const int src0 = (lane & ~3) | (cq >> 1);
    const int src1 = src0 + 2;
    const bool oddl = cq & 1;

    for (int jt = 0; jt <= jt_max; jt++) {
        CP_WAIT(1);
        __syncthreads();

        if (jt + 2 <= jt_max) issue_kv(jt + 2);
        CP_COMMIT();

        const uint32_t* Ku = (const uint32_t*)(KV + (jt % 3) * KVSTG);
        const uint32_t* Vu = Ku + 64 * SA;
        const float* madd = Ms + jt * 64;

        float s[2][8][4];
#pragma unroll
        for (int mi = 0; mi < 2; mi++)
#pragma unroll
            for (int ni = 0; ni < 8; ni++)
#pragma unroll
                for (int t = 0; t < 4; t++) s[mi][ni][t] = 0.f;
#pragma unroll
        for (int ks = 0; ks < 8; ks++) {
            const int k = ks * 8;
            uint32_t a0[2], a1[2], a2[2], a3[2];
#pragma unroll
            for (int mi = 0; mi < 2; mi++) {
                int mb = wm + mi * 16;
                a0[mi] = Qu[(mb + r) * SA + k + cq];
                a1[mi] = Qu[(mb + r + 8) * SA + k + cq];
                a2[mi] = Qu[(mb + r) * SA + k + cq + 4];
                a3[mi] = Qu[(mb + r + 8) * SA + k + cq + 4];
            }
#pragma unroll
            for (int ni = 0; ni < 8; ni++) {
                uint32_t b0 = Ku[(8 * ni + r) * SA + k + cq];
                uint32_t b1 = Ku[(8 * ni + r) * SA + k + cq + 4];
                mma_tf32(s[0][ni], a0[0], a1[0], a2[0], a3[0], b0, b1);
                mma_tf32(s[1][ni], a0[1], a1[1], a2[1], a3[1], b0, b1);
            }
        }

        const bool part = (jt * 64 + 63 > rowbase);
        const int colb = jt * 64;
#pragma unroll
        for (int mi = 0; mi < 2; mi++) {
#pragma unroll
            for (int ni = 0; ni < 8; ni++) {
#pragma unroll
                for (int t = 0; t < 4; t++) {
                    int col = 8 * ni + 2 * cq + (t & 1);
                    int rowg = rowbase + mi * 16 + r + ((t < 2) ? 0 : 8);
                    float v;
                    if (part && (colb + col > rowg)) v = NEG + madd[col];
                    else                             v = s[mi][ni][t] * 0.125f + madd[col];
                    s[mi][ni][t] = v;
                }
            }
        }

#pragma unroll
        for (int mi = 0; mi < 2; mi++) {
            float mx0 = -1e30f, mx1 = -1e30f;
#pragma unroll
            for (int ni = 0; ni < 8; ni++) {
                mx0 = fmaxf(mx0, fmaxf(s[mi][ni][0], s[mi][ni][1]));
                mx1 = fmaxf(mx1, fmaxf(s[mi][ni][2], s[mi][ni][3]));
            }
            mx0 = fmaxf(mx0, __shfl_xor_sync(0xffffffff, mx0, 1));
            mx0 = fmaxf(mx0, __shfl_xor_sync(0xffffffff, mx0, 2));
            mx1 = fmaxf(mx1, __shfl_xor_sync(0xffffffff, mx1, 1));
            mx1 = fmaxf(mx1, __shfl_xor_sync(0xffffffff, mx1, 2));

            float nm0 = fmaxf(mst[mi][0], mx0), nm1 = fmaxf(mst[mi][1], mx1);
            float sc0 = __expf(mst[mi][0] - nm0), sc1 = __expf(mst[mi][1] - nm1);
            float sum0 = 0.f, sum1 = 0.f;
#pragma unroll
            for (int ni = 0; ni < 8; ni++) {
                s[mi][ni][0] = __expf(s[mi][ni][0] - nm0);
                s[mi][ni][1] = __expf(s[mi][ni][1] - nm0);
                s[mi][ni][2] = __expf(s[mi][ni][2] - nm1);
                s[mi][ni][3] = __expf(s[mi][ni][3] - nm1);
                sum0 += s[mi][ni][0] + s[mi][ni][1];
                sum1 += s[mi][ni][2] + s[mi][ni][3];
            }
            sum0 += __shfl_xor_sync(0xffffffff, sum0, 1);
            sum0 += __shfl_xor_sync(0xffffffff, sum0, 2);
            sum1 += __shfl_xor_sync(0xffffffff, sum1, 1);
            sum1 += __shfl_xor_sync(0xffffffff, sum1, 2);

            lst[mi][0] = lst[mi][0] * sc0 + sum0;  mst[mi][0] = nm0;
            lst[mi][1] = lst[mi][1] * sc1 + sum1;  mst[mi][1] = nm1;

#pragma unroll
            for (int ni = 0; ni < 8; ni++) {
                o[mi][ni][0] *= sc0; o[mi][ni][1] *= sc0;
                o[mi][ni][2] *= sc1; o[mi][ni][3] *= sc1;
            }
        }

#pragma unroll
        for (int ks = 0; ks < 8; ks++) {
            uint32_t pa0[2], pa1[2], pa2[2], pa3[2];
#pragma unroll
            for (int mi = 0; mi < 2; mi++) {
                uint32_t q0r = f2tf32(s[mi][ks][0]), q1r = f2tf32(s[mi][ks][1]);
                uint32_t q2r = f2tf32(s[mi][ks][2]), q3r = f2tf32(s[mi][ks][3]);
                uint32_t x00 = __shfl_sync(0xffffffff, q0r, src0);
                uint32_t x01 = __shfl_sync(0xffffffff, q1r, src0);
                uint32_t x10 = __shfl_sync(0xffffffff, q2r, src0);
                uint32_t x11 = __shfl_sync(0xffffffff, q3r, src0);
                uint32_t x20 = __shfl_sync(0xffffffff, q0r, src1);
                uint32_t x21 = __shfl_sync(0xffffffff, q1r, src1);
                uint32_t x30 = __shfl_sync(0xffffffff, q2r, src1);
                uint32_t x31 = __shfl_sync(0xffffffff, q3r, src1);
                pa0[mi] = oddl ? x01 : x00;
                pa1[mi] = oddl ? x11 : x10;
                pa2[mi] = oddl ? x21 : x20;
                pa3[mi] = oddl ? x31 : x30;
            }
            const int k = ks * 8;
#pragma unroll
            for (int ni = 0; ni < 8; ni++) {
                uint32_t b0 = Vu[(k + cq) * SA + 8 * ni + r];
                uint32_t b1 = Vu[(k + cq + 4) * SA + 8 * ni + r];
                mma_tf32(o[0][ni], pa0[0], pa1[0], pa2[0], pa3[0], b0, b1);
                mma_tf32(o[1][ni], pa0[1], pa1[1], pa2[1], pa3[1], b0, b1);
            }
        }
    }

    // ---- epilogue (R10: plain float2 stores)
#pragma unroll
    for (int mi = 0; mi < 2; mi++) {
        float inv0 = 1.f / lst[mi][0], inv1 = 1.f / lst[mi][1];
        int rw0 = rowbase + mi * 16 + r;
        float* ob0 = g_att + (size_t)(b * SS + rw0) * DD + h * HD;
        float* ob1 = g_att + (size_t)(b * SS + rw0 + 8) * DD + h * HD;
#pragma unroll
        for (int ni = 0; ni < 8; ni++) {
            int col = 8 * ni + 2 * cq;
            float2 w0, w1;
            w0.x = f2tf32f(o[mi][ni][0] * inv0); w0.y = f2tf32f(o[mi][ni][1] * inv0);
            w1.x = f2tf32f(o[mi][ni][2] * inv1); w1.y = f2tf32f(o[mi][ni][3] * inv1);
            *(float2*)(ob0 + col) = w0;
            *(float2*)(ob1 + col) = w1;
        }
    }
}

// ---------------------------------------------------------------------------
extern "C" void kernel_launch(void* const* d_in, const int* in_sizes, int n_in,
                              void* d_out, int out_size)
{
    const float* x    = (const float*)d_in[0];
    const float* mask = (const float*)d_in[1];
    const float* Wq   = (const float*)d_in[2];
    const float* bq   = (const float*)d_in[3];
    const float* Wk   = (const float*)d_in[4];
    const float* bk   = (const float*)d_in[5];
    const float* Wv   = (const float*)d_in[6];
    const float* bv   = (const float*)d_in[7];
    const float* Wo   = (const float*)d_in[8];
    const float* bo   = (const float*)d_in[9];
    float* out = (float*)d_out;

    cvt_x<<<(X4 + 255) / 256, 256>>>(x);
    dim3 gw(32, 32, 4);
    cvt_w<<<gw, 256>>>(Wq, Wk, Wv, Wo);

    const int gemm_smem = 3 * (ASTG + BSTG) * sizeof(float);              // ~102 KB
    const int attn_smem = (QR * SA + 3 * KVSTG + SS) * sizeof(float);     // ~182.3 KB
    cudaFuncSetAttribute(qkv_mma,   cudaFuncAttributeMaxDynamicSharedMemorySize, gemm_smem);
    cudaFuncSetAttribute(oproj_mma, cudaFuncAttributeMaxDynamicSharedMemorySize, gemm_smem);
    cudaFuncSetAttribute(attn_mma,  cudaFuncAttributeMaxDynamicSharedMemorySize, attn_smem);

    dim3 gq(DD / 128, (BB * SS) / 128, 3);
    qkv_mma<<<gq, 128, gemm_smem>>>(bq, bk, bv);

    dim3 ga(SS / QR, HH, BB);
    attn_mma<<<ga, 256, attn_smem>>>(mask);

    dim3 go(DD / 128, (BB * SS) / 128);
    oproj_mma<<<go, 128, gemm_smem>>>(bo, out);
}

// round 13
// speedup vs baseline: 1.5521x; 1.0813x over previous
#include <cuda_runtime.h>
#include <cuda_bf16.h>
#include <cstdint>

// Problem constants
#define BB 2
#define SS 2048
#define DD 1024
#define HH 16
#define HD 64
#define NEG (-1.0e9f)

// Scratch (device globals)
__device__ float g_q[BB * HH * SS * HD];     // [B,H,S,HD]  (tf32-rounded)
__device__ float g_k[BB * HH * SS * HD];
__device__ float g_v[BB * HH * SS * HD];
__device__ float g_att[BB * SS * DD];        // [B,S,D]     (tf32-rounded)
__device__ float g_xc[BB * SS * DD];         // tf32-rounded x
__device__ float g_wq[DD * DD];              // tf32-rounded weights
__device__ float g_wk[DD * DD];
__device__ float g_wv[DD * DD];
__device__ float g_wo[DD * DD];

// ===========================================================================
// helpers
// ===========================================================================
__device__ __forceinline__ uint32_t f2tf32(float f) {
    uint32_t u;
    asm("cvt.rna.tf32.f32 %0, %1;" : "=r"(u) : "f"(f));
    return u;
}
__device__ __forceinline__ float f2tf32f(float f) {
    return __uint_as_float(f2tf32(f));
}

__device__ __forceinline__ uint32_t smem_u32(const void* p) {
    uint32_t a;
    asm("{ .reg .u64 t; cvta.to.shared.u64 t, %1; cvt.u32.u64 %0, t; }"
        : "=r"(a) : "l"(p));
    return a;
}

__device__ __forceinline__ void cp16(uint32_t dst, const void* src) {
    asm volatile("cp.async.ca.shared.global [%0], [%1], 16;"
                 :: "r"(dst), "l"(src));
}
#define CP_COMMIT() asm volatile("cp.async.commit_group;" ::: "memory")
#define CP_WAIT(N)  asm volatile("cp.async.wait_group %0;" :: "n"(N) : "memory")

__device__ __forceinline__ void mma_tf32(
    float* c, uint32_t a0, uint32_t a1, uint32_t a2, uint32_t a3,
    uint32_t b0, uint32_t b1)
{
    asm volatile(
        "mma.sync.aligned.m16n8k8.row.col.f32.tf32.tf32.f32 "
        "{%0,%1,%2,%3}, {%4,%5,%6,%7}, {%8,%9}, {%0,%1,%2,%3};"
        : "+f"(c[0]), "+f"(c[1]), "+f"(c[2]), "+f"(c[3])
        : "r"(a0), "r"(a1), "r"(a2), "r"(a3), "r"(b0), "r"(b1));
}

// ===========================================================================
// merged tf32 pre-round pass (x + 4 weight matrices, one launch) — R10 exact
// ===========================================================================
#define X4 (BB * SS * DD / 4)
#define W4 (DD * DD / 4)

__global__ __launch_bounds__(256) void cvt_all(
    const float* __restrict__ x,
    const float* __restrict__ Wq, const float* __restrict__ Wk,
    const float* __restrict__ Wv, const float* __restrict__ Wo)
{
    int i = blockIdx.x * blockDim.x + threadIdx.x;
    const float4* src;
    float4* dst;
    int off;
    if (i < X4) {
        src = (const float4*)x; dst = (float4*)g_xc; off = i;
    } else {
        int j = i - X4;
        int seg = j / W4;
        off = j - seg * W4;
        src = (seg == 0) ? (const float4*)Wq : (seg == 1) ? (const float4*)Wk
            : (seg == 2) ? (const float4*)Wv : (const float4*)Wo;
        dst = (seg == 0) ? (float4*)g_wq : (seg == 1) ? (float4*)g_wk
            : (seg == 2) ? (float4*)g_wv : (float4*)g_wo;
        if (seg > 3) return;
    }
    float4 v = src[off];
    float4 q;
    q.x = f2tf32f(v.x); q.y = f2tf32f(v.y);
    q.z = f2tf32f(v.z); q.w = f2tf32f(v.w);
    dst[off] = q;
}

// ===========================================================================
// tf32 mma.sync GEMM — R10 exact: 128 threads, warp tile 64x64, BK=32,
// 3-stage cp.async ring, 2 CTAs/SM.
// ===========================================================================
#define STRA 36
#define STRB 136
#define ASZ (128 * STRA)
#define BSZ (32 * STRB)

__device__ __forceinline__ void gemm_issue(
    const float* __restrict__ A, const float* __restrict__ W,
    int m0, int n0, int c, uint32_t as_u, uint32_t bs_u, int tid)
{
#pragma unroll
    for (int i = 0; i < 8; i++) {
        int lin = i * 512 + tid * 4;
        int row = lin >> 5, col = lin & 31;
        cp16(as_u + (uint32_t)(row * STRA + col) * 4,
             A + (size_t)(m0 + row) * DD + c * 32 + col);
        int kr = lin >> 7, nc = lin & 127;
        cp16(bs_u + (uint32_t)(kr * STRB + nc) * 4,
             W + (size_t)(c * 32 + kr) * DD + n0 + nc);
    }
}

__device__ __forceinline__ void tc_mainloop(
    const float* __restrict__ A, const float* __restrict__ W,
    int m0, int n0, float acc[4][8][4], float* AsG, float* BsG)
{
    const int tid = threadIdx.x;
    const int warp = tid >> 5, lane = tid & 31;
    const int wm0 = (warp & 1) * 64;
    const int wn0 = (warp >> 1) * 64;
    const int r = lane >> 2, cq = lane & 3;

    const uint32_t as_u = smem_u32(AsG);
    const uint32_t bs_u = smem_u32(BsG);

#pragma unroll
    for (int mi = 0; mi < 4; mi++)
#pragma unroll
        for (int ni = 0; ni < 8; ni++)
#pragma unroll
            for (int t = 0; t < 4; t++) acc[mi][ni][t] = 0.f;

    gemm_issue(A, W, m0, n0, 0, as_u, bs_u, tid); CP_COMMIT();
    gemm_issue(A, W, m0, n0, 1, as_u + ASZ * 4, bs_u + BSZ * 4, tid); CP_COMMIT();

    for (int c = 0; c < 32; c++) {
        CP_WAIT(1);
        __syncthreads();

        if (c < 30) {
            int s = (c + 2) % 3;
            gemm_issue(A, W, m0, n0, c + 2,
                       as_u + (uint32_t)(s * ASZ) * 4,
                       bs_u + (uint32_t)(s * BSZ) * 4, tid);
        }
        CP_COMMIT();

        const uint32_t* Asu = (const uint32_t*)(AsG + (c % 3) * ASZ);
        const uint32_t* Bsu = (const uint32_t*)(BsG + (c % 3) * BSZ);
#pragma unroll
        for (int ks = 0; ks < 4; ks++) {
            const int k = ks * 8;
            uint32_t af[4][4], bf[8][2];
#pragma unroll
            for (int mi = 0; mi < 4; mi++) {
                int mb = wm0 + mi * 16;
                af[mi][0] = Asu[(mb + r) * STRA + k + cq];
                af[mi][1] = Asu[(mb + r + 8) * STRA + k + cq];
                af[mi][2] = Asu[(mb + r) * STRA + k + cq + 4];
                af[mi][3] = Asu[(mb + r + 8) * STRA + k + cq + 4];
            }
#pragma unroll
            for (int ni = 0; ni < 8; ni++) {
                int nb = wn0 + ni * 8;
                bf[ni][0] = Bsu[(k + cq) * STRB + nb + r];
                bf[ni][1] = Bsu[(k + cq + 4) * STRB + nb + r];
            }
#pragma unroll
            for (int mi = 0; mi < 4; mi++)
#pragma unroll
                for (int ni = 0; ni < 8; ni++)
                    mma_tf32(acc[mi][ni], af[mi][0], af[mi][1], af[mi][2], af[mi][3],
                             bf[ni][0], bf[ni][1]);
        }
    }
}

// ---------------------------------------------------------------------------
__global__ __launch_bounds__(128, 2) void qkv_mma(
    const float* __restrict__ bq, const float* __restrict__ bk,
    const float* __restrict__ bv)
{
    extern __shared__ float dsm[];
    float* AsG = dsm;
    float* BsG = dsm + 3 * ASZ;

    const int z = blockIdx.z;
    const float* __restrict__ W = (z == 0) ? g_wq : (z == 1) ? g_wk : g_wv;
    const float* __restrict__ bias = (z == 0) ? bq : (z == 1) ? bk : bv;
    float* __restrict__ out = (z == 0) ? g_q : (z == 1) ? g_k : g_v;

    const int m0 = blockIdx.y * 128;
    const int n0 = blockIdx.x * 128;

    float acc[4][8][4];
    tc_mainloop(g_xc, W, m0, n0, acc, AsG, BsG);

    const int tid = threadIdx.x;
    const int warp = tid >> 5, lane = tid & 31;
    const int wm0 = (warp & 1) * 64;
    const int wn0 = (warp >> 1) * 64;
    const int r = lane >> 2, cq = lane & 3;

#pragma unroll
    for (int mi = 0; mi < 4; mi++) {
#pragma unroll
        for (int ni = 0; ni < 8; ni++) {
            int ncol = n0 + wn0 + ni * 8 + 2 * cq;
            int h = ncol >> 6, d = ncol & 63;
            float b0v = bias[ncol], b1v = bias[ncol + 1];
#pragma unroll
            for (int half = 0; half < 2; half++) {
                int mrow = m0 + wm0 + mi * 16 + r + half * 8;
                int bidx = mrow >> 11, s = mrow & (SS - 1);
                float2 o;
                o.x = f2tf32f(acc[mi][ni][half * 2 + 0] + b0v);
                o.y = f2tf32f(acc[mi][ni][half * 2 + 1] + b1v);
                *(float2*)(out + (size_t)((bidx * HH + h) * SS + s) * HD + d) = o;
            }
        }
    }
}

// ---------------------------------------------------------------------------
__global__ __launch_bounds__(128, 2) void oproj_mma(
    const float* __restrict__ bo, float* __restrict__ out)
{
    extern __shared__ float dsm[];
    float* AsG = dsm;
    float* BsG = dsm + 3 * ASZ;

    const int m0 = blockIdx.y * 128;
    const int n0 = blockIdx.x * 128;

    float acc[4][8][4];
    tc_mainloop(g_att, g_wo, m0, n0, acc, AsG, BsG);

    const int tid = threadIdx.x;
    const int warp = tid >> 5, lane = tid & 31;
    const int wm0 = (warp & 1) * 64;
    const int wn0 = (warp >> 1) * 64;
    const int r = lane >> 2, cq = lane & 3;

#pragma unroll
    for (int mi = 0; mi < 4; mi++) {
#pragma unroll
        for (int ni = 0; ni < 8; ni++) {
            int ncol = n0 + wn0 + ni * 8 + 2 * cq;
            float b0v = bo[ncol], b1v = bo[ncol + 1];
#pragma unroll
            for (int half = 0; half < 2; half++) {
                int mrow = m0 + wm0 + mi * 16 + r + half * 8;
                float2 o;
                o.x = acc[mi][ni][half * 2 + 0] + b0v;
                o.y = acc[mi][ni][half * 2 + 1] + b1v;
                *(float2*)(out + (size_t)mrow * DD + ncol) = o;
            }
        }
    }
}

// ===========================================================================
// Flash attention, tf32 mma.sync.
// 128 q-rows/block, 128 threads = 4 warps, 32 q-rows per warp (2 m-tiles —
// same warp tile & fragment algebra as R12). 2-stage cp.async KV ring with
// ONE __syncthreads per tile; mask preloaded. 2 CTAs/SM.
// ===========================================================================
#define SA 68
#define QR 128
#define KVSTG (2 * 64 * SA)

__global__ __launch_bounds__(128, 2) void attn_mma(const float* __restrict__ mask)
{
    extern __shared__ float smf[];
    float* Qs = smf;                      // [128][SA]
    float* KV = Qs + QR * SA;             // 2 stages x (K[64*SA] + V[64*SA])
    float* Ms = KV + 2 * KVSTG;           // [2048] additive mask row

    const uint32_t* Qu = (const uint32_t*)Qs;
    const uint32_t qs_u = smem_u32(Qs);
    const uint32_t kv_u = smem_u32(KV);

    const int qt = gridDim.x - 1 - blockIdx.x;   // big tiles first
    const int h = blockIdx.y, b = blockIdx.z;
    const int tid = threadIdx.x, warp = tid >> 5, lane = tid & 31;
    const int r = lane >> 2, cq = lane & 3;
    const int wm = warp * 32;                    // 32 rows per warp
    const int q0 = qt * QR;

    const float* kroot = g_k + (size_t)((b * HH + h) * SS) * HD;
    const float* vroot = g_v + (size_t)((b * HH + h) * SS) * HD;

    // Q tile (cp.async): 128 rows x 64, 16 cp16/thread
    const float* qbase = g_q + (size_t)((b * HH + h) * SS + q0) * HD;
#pragma unroll
    for (int p = 0; p < 16; p++) {
        int lin = p * 512 + tid * 4;
        int rr = lin >> 6, dd = lin & 63;
        cp16(qs_u + (uint32_t)(rr * SA + dd) * 4, qbase + rr * 64 + dd);
    }

    auto issue_kv = [&](int jt) {
        int st = jt & 1;
        uint32_t ku = kv_u + (uint32_t)(st * KVSTG) * 4;
        uint32_t vu = ku + (uint32_t)(64 * SA) * 4;
        const float* kb = kroot + (size_t)(jt * 64) * HD;
        const float* vb = vroot + (size_t)(jt * 64) * HD;
#pragma unroll
        for (int p = 0; p < 8; p++) {
            int lin = p * 512 + tid * 4;
            int rr = lin >> 6, dd = lin & 63;
            uint32_t off = (uint32_t)(rr * SA + dd) * 4;
            cp16(ku + off, kb + rr * 64 + dd);
            cp16(vu + off, vb + rr * 64 + dd);
        }
    };

    issue_kv(0);
    CP_COMMIT();     // group: Q + KV0

    // Preload additive mask row (plain stores; visible after first sync)
#pragma unroll
    for (int p = 0; p < 16; p++) {
        int idx = p * 128 + tid;
        Ms[idx] = (1.f - mask[b * SS + idx]) * NEG;
    }

    float o[2][8][4];
#pragma unroll
    for (int mi = 0; mi < 2; mi++)
#pragma unroll
        for (int ni = 0; ni < 8; ni++)
#pragma unroll
            for (int t = 0; t < 4; t++) o[mi][ni][t] = 0.f;
    float mst[2][2] = {{-1e30f, -1e30f}, {-1e30f, -1e30f}};
    float lst[2][2] = {{0.f, 0.f}, {0.f, 0.f}};

    const int jt_max = 2 * qt + 1;
    const int rowbase = q0 + wm;
    const int src0 = (lane & ~3) | (cq >> 1);
    const int src1 = src0 + 2;
    const bool oddl = cq & 1;

    for (int jt = 0; jt <= jt_max; jt++) {
        CP_WAIT(0);          // stage jt resident (prefetched a full tile ago)
        __syncthreads();     // + readers of the other stage (tile jt-1) done

        if (jt < jt_max) { issue_kv(jt + 1); CP_COMMIT(); }

        const uint32_t* Ku = (const uint32_t*)(KV + (jt & 1) * KVSTG);
        const uint32_t* Vu = Ku + 64 * SA;
        const float* madd = Ms + jt * 64;

        // ---- S = Q @ K^T  (both m-tiles share each K B-fragment)
        float s[2][8][4];
#pragma unroll
        for (int mi = 0; mi < 2; mi++)
#pragma unroll
            for (int ni = 0; ni < 8; ni++)
#pragma unroll
                for (int t = 0; t < 4; t++) s[mi][ni][t] = 0.f;
#pragma unroll
        for (int ks = 0; ks < 8; ks++) {
            const int k = ks * 8;
            uint32_t a0[2], a1[2], a2[2], a3[2];
#pragma unroll
            for (int mi = 0; mi < 2; mi++) {
                int mb = wm + mi * 16;
                a0[mi] = Qu[(mb + r) * SA + k + cq];
                a1[mi] = Qu[(mb + r + 8) * SA + k + cq];
                a2[mi] = Qu[(mb + r) * SA + k + cq + 4];
                a3[mi] = Qu[(mb + r + 8) * SA + k + cq + 4];
            }
#pragma unroll
            for (int ni = 0; ni < 8; ni++) {
                uint32_t b0 = Ku[(8 * ni + r) * SA + k + cq];
                uint32_t b1 = Ku[(8 * ni + r) * SA + k + cq + 4];
                mma_tf32(s[0][ni], a0[0], a1[0], a2[0], a3[0], b0, b1);
                mma_tf32(s[1][ni], a0[1], a1[1], a2[1], a3[1], b0, b1);
            }
        }

        // ---- scale + causal + padding mask
        const bool part = (jt * 64 + 63 > rowbase);
        const int colb = jt * 64;
#pragma unroll
        for (int mi = 0; mi < 2; mi++) {
#pragma unroll
            for (int ni = 0; ni < 8; ni++) {
#pragma unroll
                for (int t = 0; t < 4; t++) {
                    int col = 8 * ni + 2 * cq + (t & 1);
                    int rowg = rowbase + mi * 16 + r + ((t < 2) ? 0 : 8);
                    float v;
                    if (part && (colb + col > rowg)) v = NEG + madd[col];
                    else                             v = s[mi][ni][t] * 0.125f + madd[col];
                    s[mi][ni][t] = v;
                }
            }
        }

        // ---- online softmax
#pragma unroll
        for (int mi = 0; mi < 2; mi++) {
            float mx0 = -1e30f, mx1 = -1e30f;
#pragma unroll
            for (int ni = 0; ni < 8; ni++) {
                mx0 = fmaxf(mx0, fmaxf(s[mi][ni][0], s[mi][ni][1]));
                mx1 = fmaxf(mx1, fmaxf(s[mi][ni][2], s[mi][ni][3]));
            }
            mx0 = fmaxf(mx0, __shfl_xor_sync(0xffffffff, mx0, 1));
            mx0 = fmaxf(mx0, __shfl_xor_sync(0xffffffff, mx0, 2));
            mx1 = fmaxf(mx1, __shfl_xor_sync(0xffffffff, mx1, 1));
            mx1 = fmaxf(mx1, __shfl_xor_sync(0xffffffff, mx1, 2));

            float nm0 = fmaxf(mst[mi][0], mx0), nm1 = fmaxf(mst[mi][1], mx1);
            float sc0 = __expf(mst[mi][0] - nm0), sc1 = __expf(mst[mi][1] - nm1);
            float sum0 = 0.f, sum1 = 0.f;
#pragma unroll
            for (int ni = 0; ni < 8; ni++) {
                s[mi][ni][0] = __expf(s[mi][ni][0] - nm0);
                s[mi][ni][1] = __expf(s[mi][ni][1] - nm0);
                s[mi][ni][2] = __expf(s[mi][ni][2] - nm1);
                s[mi][ni][3] = __expf(s[mi][ni][3] - nm1);
                sum0 += s[mi][ni][0] + s[mi][ni][1];
                sum1 += s[mi][ni][2] + s[mi][ni][3];
            }
            sum0 += __shfl_xor_sync(0xffffffff, sum0, 1);
            sum0 += __shfl_xor_sync(0xffffffff, sum0, 2);
            sum1 += __shfl_xor_sync(0xffffffff, sum1, 1);
            sum1 += __shfl_xor_sync(0xffffffff, sum1, 2);

            lst[mi][0] = lst[mi][0] * sc0 + sum0;  mst[mi][0] = nm0;
            lst[mi][1] = lst[mi][1] * sc1 + sum1;  mst[mi][1] = nm1;

#pragma unroll
            for (int ni = 0; ni < 8; ni++) {
                o[mi][ni][0] *= sc0; o[mi][ni][1] *= sc0;
                o[mi][ni][2] *= sc1; o[mi][ni][3] *= sc1;
            }
        }

        // ---- O += P @ V : shuffle C->A fragment conversion; V shared by mi
#pragma unroll
        for (int ks = 0; ks < 8; ks++) {
            uint32_t pa0[2], pa1[2], pa2[2], pa3[2];
#pragma unroll
            for (int mi = 0; mi < 2; mi++) {
                uint32_t q0r = f2tf32(s[mi][ks][0]), q1r = f2tf32(s[mi][ks][1]);
                uint32_t q2r = f2tf32(s[mi][ks][2]), q3r = f2tf32(s[mi][ks][3]);
                uint32_t x00 = __shfl_sync(0xffffffff, q0r, src0);
                uint32_t x01 = __shfl_sync(0xffffffff, q1r, src0);
                uint32_t x10 = __shfl_sync(0xffffffff, q2r, src0);
                uint32_t x11 = __shfl_sync(0xffffffff, q3r, src0);
                uint32_t x20 = __shfl_sync(0xffffffff, q0r, src1);
                uint32_t x21 = __shfl_sync(0xffffffff, q1r, src1);
                uint32_t x30 = __shfl_sync(0xffffffff, q2r, src1);
                uint32_t x31 = __shfl_sync(0xffffffff, q3r, src1);
                pa0[mi] = oddl ? x01 : x00;
                pa1[mi] = oddl ? x11 : x10;
                pa2[mi] = oddl ? x21 : x20;
                pa3[mi] = oddl ? x31 : x30;
            }
            const int k = ks * 8;
#pragma unroll
            for (int ni = 0; ni < 8; ni++) {
                uint32_t b0 = Vu[(k + cq) * SA + 8 * ni + r];
                uint32_t b1 = Vu[(k + cq + 4) * SA + 8 * ni + r];
                mma_tf32(o[0][ni], pa0[0], pa1[0], pa2[0], pa3[0], b0, b1);
                mma_tf32(o[1][ni], pa0[1], pa1[1], pa2[1], pa3[1], b0, b1);
            }
        }
    }

    // ---- epilogue
#pragma unroll
    for (int mi = 0; mi < 2; mi++) {
        float inv0 = 1.f / lst[mi][0], inv1 = 1.f / lst[mi][1];
        int rw0 = rowbase + mi * 16 + r;
        float* ob0 = g_att + (size_t)(b * SS + rw0) * DD + h * HD;
        float* ob1 = g_att + (size_t)(b * SS + rw0 + 8) * DD + h * HD;
#pragma unroll
        for (int ni = 0; ni < 8; ni++) {
            int col = 8 * ni + 2 * cq;
            float2 w0, w1;
            w0.x = f2tf32f(o[mi][ni][0] * inv0); w0.y = f2tf32f(o[mi][ni][1] * inv0);
            w1.x = f2tf32f(o[mi][ni][2] * inv1); w1.y = f2tf32f(o[mi][ni][3] * inv1);
            *(float2*)(ob0 + col) = w0;
            *(float2*)(ob1 + col) = w1;
        }
    }
}

// ---------------------------------------------------------------------------
extern "C" void kernel_launch(void* const* d_in, const int* in_sizes, int n_in,
                              void* d_out, int out_size)
{
    const float* x    = (const float*)d_in[0];
    const float* mask = (const float*)d_in[1];
    const float* Wq   = (const float*)d_in[2];
    const float* bq   = (const float*)d_in[3];
    const float* Wk   = (const float*)d_in[4];
    const float* bk   = (const float*)d_in[5];
    const float* Wv   = (const float*)d_in[6];
    const float* bv   = (const float*)d_in[7];
    const float* Wo   = (const float*)d_in[8];
    const float* bo   = (const float*)d_in[9];
    float* out = (float*)d_out;

    const int cvt_total = X4 + 4 * W4;
    cvt_all<<<(cvt_total + 255) / 256, 256>>>(x, Wq, Wk, Wv, Wo);

    const int gemm_smem = 3 * (ASZ + BSZ) * sizeof(float);                 // ~107.5 KB
    const int attn_smem = (QR * SA + 2 * KVSTG + SS) * sizeof(float);      // ~110 KB
    cudaFuncSetAttribute(qkv_mma,   cudaFuncAttributeMaxDynamicSharedMemorySize, gemm_smem);
    cudaFuncSetAttribute(oproj_mma, cudaFuncAttributeMaxDynamicSharedMemorySize, gemm_smem);
    cudaFuncSetAttribute(attn_mma,  cudaFuncAttributeMaxDynamicSharedMemorySize, attn_smem);

    dim3 gq(DD / 128, (BB * SS) / 128, 3);
    qkv_mma<<<gq, 128, gemm_smem>>>(bq, bk, bv);

    dim3 ga(SS / QR, HH, BB);
    attn_mma<<<ga, 128, attn_smem>>>(mask);

    dim3 go(DD / 128, (BB * SS) / 128);
    oproj_mma<<<go, 128, gemm_smem>>>(bo, out);
}

// round 14
// speedup vs baseline: 1.5550x; 1.0019x over previous
#include <cuda_runtime.h>
#include <cuda_bf16.h>
#include <cstdint>

// Problem constants
#define BB 2
#define SS 2048
#define DD 1024
#define HH 16
#define HD 64
#define NEG (-1.0e9f)

// Scratch (device globals)
__device__ float g_q[BB * HH * SS * HD];     // [B,H,S,HD]  (tf32-rounded)
__device__ float g_k[BB * HH * SS * HD];
__device__ float g_v[BB * HH * SS * HD];
__device__ float g_att[BB * SS * DD];        // [B,S,D]     (tf32-rounded)
__device__ float g_xc[BB * SS * DD];         // tf32-rounded x
__device__ float g_wq[DD * DD];              // tf32-rounded weights
__device__ float g_wk[DD * DD];
__device__ float g_wv[DD * DD];
__device__ float g_wo[DD * DD];

// ===========================================================================
// helpers
// ===========================================================================
__device__ __forceinline__ uint32_t f2tf32(float f) {
    uint32_t u;
    asm("cvt.rna.tf32.f32 %0, %1;" : "=r"(u) : "f"(f));
    return u;
}
__device__ __forceinline__ float f2tf32f(float f) {
    return __uint_as_float(f2tf32(f));
}

__device__ __forceinline__ uint32_t smem_u32(const void* p) {
    uint32_t a;
    asm("{ .reg .u64 t; cvta.to.shared.u64 t, %1; cvt.u32.u64 %0, t; }"
        : "=r"(a) : "l"(p));
    return a;
}

__device__ __forceinline__ void cp16(uint32_t dst, const void* src) {
    asm volatile("cp.async.ca.shared.global [%0], [%1], 16;"
                 :: "r"(dst), "l"(src));
}
#define CP_COMMIT() asm volatile("cp.async.commit_group;" ::: "memory")
#define CP_WAIT(N)  asm volatile("cp.async.wait_group %0;" :: "n"(N) : "memory")

__device__ __forceinline__ void mma_tf32(
    float* c, uint32_t a0, uint32_t a1, uint32_t a2, uint32_t a3,
    uint32_t b0, uint32_t b1)
{
    asm volatile(
        "mma.sync.aligned.m16n8k8.row.col.f32.tf32.tf32.f32 "
        "{%0,%1,%2,%3}, {%4,%5,%6,%7}, {%8,%9}, {%0,%1,%2,%3};"
        : "+f"(c[0]), "+f"(c[1]), "+f"(c[2]), "+f"(c[3])
        : "r"(a0), "r"(a1), "r"(a2), "r"(a3), "r"(b0), "r"(b1));
}

// ===========================================================================
// merged tf32 pre-round pass (x + 4 weight matrices, one launch)
// ===========================================================================
#define X4 (BB * SS * DD / 4)
#define W4 (DD * DD / 4)

__global__ __launch_bounds__(256) void cvt_all(
    const float* __restrict__ x,
    const float* __restrict__ Wq, const float* __restrict__ Wk,
    const float* __restrict__ Wv, const float* __restrict__ Wo)
{
    int i = blockIdx.x * blockDim.x + threadIdx.x;
    const float4* src;
    float4* dst;
    int off;
    if (i < X4) {
        src = (const float4*)x; dst = (float4*)g_xc; off = i;
    } else {
        int j = i - X4;
        int seg = j / W4;
        off = j - seg * W4;
        src = (seg == 0) ? (const float4*)Wq : (seg == 1) ? (const float4*)Wk
            : (seg == 2) ? (const float4*)Wv : (const float4*)Wo;
        dst = (seg == 0) ? (float4*)g_wq : (seg == 1) ? (float4*)g_wk
            : (seg == 2) ? (float4*)g_wv : (float4*)g_wo;
        if (seg > 3) return;
    }
    float4 v = src[off];
    float4 q;
    q.x = f2tf32f(v.x); q.y = f2tf32f(v.y);
    q.z = f2tf32f(v.z); q.w = f2tf32f(v.w);
    dst[off] = q;
}

// ===========================================================================
// tf32 mma.sync GEMM — R13 exact: 128 threads, warp tile 64x64, BK=32,
// 3-stage cp.async ring, 2 CTAs/SM.
// ===========================================================================
#define STRA 36
#define STRB 136
#define ASZ (128 * STRA)
#define BSZ (32 * STRB)

__device__ __forceinline__ void gemm_issue(
    const float* __restrict__ A, const float* __restrict__ W,
    int m0, int n0, int c, uint32_t as_u, uint32_t bs_u, int tid)
{
#pragma unroll
    for (int i = 0; i < 8; i++) {
        int lin = i * 512 + tid * 4;
        int row = lin >> 5, col = lin & 31;
        cp16(as_u + (uint32_t)(row * STRA + col) * 4,
             A + (size_t)(m0 + row) * DD + c * 32 + col);
        int kr = lin >> 7, nc = lin & 127;
        cp16(bs_u + (uint32_t)(kr * STRB + nc) * 4,
             W + (size_t)(c * 32 + kr) * DD + n0 + nc);
    }
}

__device__ __forceinline__ void tc_mainloop(
    const float* __restrict__ A, const float* __restrict__ W,
    int m0, int n0, float acc[4][8][4], float* AsG, float* BsG)
{
    const int tid = threadIdx.x;
    const int warp = tid >> 5, lane = tid & 31;
    const int wm0 = (warp & 1) * 64;
    const int wn0 = (warp >> 1) * 64;
    const int r = lane >> 2, cq = lane & 3;

    const uint32_t as_u = smem_u32(AsG);
    const uint32_t bs_u = smem_u32(BsG);

#pragma unroll
    for (int mi = 0; mi < 4; mi++)
#pragma unroll
        for (int ni = 0; ni < 8; ni++)
#pragma unroll
            for (int t = 0; t < 4; t++) acc[mi][ni][t] = 0.f;

    gemm_issue(A, W, m0, n0, 0, as_u, bs_u, tid); CP_COMMIT();
    gemm_issue(A, W, m0, n0, 1, as_u + ASZ * 4, bs_u + BSZ * 4, tid); CP_COMMIT();

    for (int c = 0; c < 32; c++) {
        CP_WAIT(1);
        __syncthreads();

        if (c < 30) {
            int s = (c + 2) % 3;
            gemm_issue(A, W, m0, n0, c + 2,
                       as_u + (uint32_t)(s * ASZ) * 4,
                       bs_u + (uint32_t)(s * BSZ) * 4, tid);
        }
        CP_COMMIT();

        const uint32_t* Asu = (const uint32_t*)(AsG + (c % 3) * ASZ);
        const uint32_t* Bsu = (const uint32_t*)(BsG + (c % 3) * BSZ);
#pragma unroll
        for (int ks = 0; ks < 4; ks++) {
            const int k = ks * 8;
            uint32_t af[4][4], bf[8][2];
#pragma unroll
            for (int mi = 0; mi < 4; mi++) {
                int mb = wm0 + mi * 16;
                af[mi][0] = Asu[(mb + r) * STRA + k + cq];
                af[mi][1] = Asu[(mb + r + 8) * STRA + k + cq];
                af[mi][2] = Asu[(mb + r) * STRA + k + cq + 4];
                af[mi][3] = Asu[(mb + r + 8) * STRA + k + cq + 4];
            }
#pragma unroll
            for (int ni = 0; ni < 8; ni++) {
                int nb = wn0 + ni * 8;
                bf[ni][0] = Bsu[(k + cq) * STRB + nb + r];
                bf[ni][1] = Bsu[(k + cq + 4) * STRB + nb + r];
            }
#pragma unroll
            for (int mi = 0; mi < 4; mi++)
#pragma unroll
                for (int ni = 0; ni < 8; ni++)
                    mma_tf32(acc[mi][ni], af[mi][0], af[mi][1], af[mi][2], af[mi][3],
                             bf[ni][0], bf[ni][1]);
        }
    }
}

// ---------------------------------------------------------------------------
__global__ __launch_bounds__(128, 2) void qkv_mma(
    const float* __restrict__ bq, const float* __restrict__ bk,
    const float* __restrict__ bv)
{
    extern __shared__ float dsm[];
    float* AsG = dsm;
    float* BsG = dsm + 3 * ASZ;

    const int z = blockIdx.z;
    const float* __restrict__ W = (z == 0) ? g_wq : (z == 1) ? g_wk : g_wv;
    const float* __restrict__ bias = (z == 0) ? bq : (z == 1) ? bk : bv;
    float* __restrict__ out = (z == 0) ? g_q : (z == 1) ? g_k : g_v;

    const int m0 = blockIdx.y * 128;
    const int n0 = blockIdx.x * 128;

    float acc[4][8][4];
    tc_mainloop(g_xc, W, m0, n0, acc, AsG, BsG);

    const int tid = threadIdx.x;
    const int warp = tid >> 5, lane = tid & 31;
    const int wm0 = (warp & 1) * 64;
    const int wn0 = (warp >> 1) * 64;
    const int r = lane >> 2, cq = lane & 3;

#pragma unroll
    for (int mi = 0; mi < 4; mi++) {
#pragma unroll
        for (int ni = 0; ni < 8; ni++) {
            int ncol = n0 + wn0 + ni * 8 + 2 * cq;
            int h = ncol >> 6, d = ncol & 63;
            float b0v = bias[ncol], b1v = bias[ncol + 1];
#pragma unroll
            for (int half = 0; half < 2; half++) {
                int mrow = m0 + wm0 + mi * 16 + r + half * 8;
                int bidx = mrow >> 11, s = mrow & (SS - 1);
                float2 o;
                o.x = f2tf32f(acc[mi][ni][half * 2 + 0] + b0v);
                o.y = f2tf32f(acc[mi][ni][half * 2 + 1] + b1v);
                *(float2*)(out + (size_t)((bidx * HH + h) * SS + s) * HD + d) = o;
            }
        }
    }
}

// ---------------------------------------------------------------------------
__global__ __launch_bounds__(128, 2) void oproj_mma(
    const float* __restrict__ bo, float* __restrict__ out)
{
    extern __shared__ float dsm[];
    float* AsG = dsm;
    float* BsG = dsm + 3 * ASZ;

    const int m0 = blockIdx.y * 128;
    const int n0 = blockIdx.x * 128;

    float acc[4][8][4];
    tc_mainloop(g_att, g_wo, m0, n0, acc, AsG, BsG);

    const int tid = threadIdx.x;
    const int warp = tid >> 5, lane = tid & 31;
    const int wm0 = (warp & 1) * 64;
    const int wn0 = (warp >> 1) * 64;
    const int r = lane >> 2, cq = lane & 3;

#pragma unroll
    for (int mi = 0; mi < 4; mi++) {
#pragma unroll
        for (int ni = 0; ni < 8; ni++) {
            int ncol = n0 + wn0 + ni * 8 + 2 * cq;
            float b0v = bo[ncol], b1v = bo[ncol + 1];
#pragma unroll
            for (int half = 0; half < 2; half++) {
                int mrow = m0 + wm0 + mi * 16 + r + half * 8;
                float2 o;
                o.x = acc[mi][ni][half * 2 + 0] + b0v;
                o.y = acc[mi][ni][half * 2 + 1] + b1v;
                *(float2*)(out + (size_t)mrow * DD + ncol) = o;
            }
        }
    }
}

// ===========================================================================
// Flash attention, tf32 mma.sync — R13 structure (128 q-rows, 4 warps,
// 2-stage KV ring, 1 sync/tile, 2 CTAs/SM) with issue-slot trims:
//   - mask values register-cached per tile (8 LDS.64, shared across mi/t)
//   - warp-uniform branch on causal-partial tiles
// ===========================================================================
#define SA 68
#define QR 128
#define KVSTG (2 * 64 * SA)

__global__ __launch_bounds__(128, 2) void attn_mma(const float* __restrict__ mask)
{
    extern __shared__ float smf[];
    float* Qs = smf;                      // [128][SA]
    float* KV = Qs + QR * SA;             // 2 stages x (K[64*SA] + V[64*SA])
    float* Ms = KV + 2 * KVSTG;           // [2048] additive mask row

    const uint32_t* Qu = (const uint32_t*)Qs;
    const uint32_t qs_u = smem_u32(Qs);
    const uint32_t kv_u = smem_u32(KV);

    const int qt = gridDim.x - 1 - blockIdx.x;   // big tiles first
    const int h = blockIdx.y, b = blockIdx.z;
    const int tid = threadIdx.x, warp = tid >> 5, lane = tid & 31;
    const int r = lane >> 2, cq = lane & 3;
    const int wm = warp * 32;                    // 32 rows per warp
    const int q0 = qt * QR;

    const float* kroot = g_k + (size_t)((b * HH + h) * SS) * HD;
    const float* vroot = g_v + (size_t)((b * HH + h) * SS) * HD;

    // Q tile (cp.async): 128 rows x 64, 16 cp16/thread
    const float* qbase = g_q + (size_t)((b * HH + h) * SS + q0) * HD;
#pragma unroll
    for (int p = 0; p < 16; p++) {
        int lin = p * 512 + tid * 4;
        int rr = lin >> 6, dd = lin & 63;
        cp16(qs_u + (uint32_t)(rr * SA + dd) * 4, qbase + rr * 64 + dd);
    }

    auto issue_kv = [&](int jt) {
        int st = jt & 1;
        uint32_t ku = kv_u + (uint32_t)(st * KVSTG) * 4;
        uint32_t vu = ku + (uint32_t)(64 * SA) * 4;
        const float* kb = kroot + (size_t)(jt * 64) * HD;
        const float* vb = vroot + (size_t)(jt * 64) * HD;
#pragma unroll
        for (int p = 0; p < 8; p++) {
            int lin = p * 512 + tid * 4;
            int rr = lin >> 6, dd = lin & 63;
            uint32_t off = (uint32_t)(rr * SA + dd) * 4;
            cp16(ku + off, kb + rr * 64 + dd);
            cp16(vu + off, vb + rr * 64 + dd);
        }
    };

    issue_kv(0);
    CP_COMMIT();     // group: Q + KV0

    // Preload additive mask row (plain stores; visible after first sync)
#pragma unroll
    for (int p = 0; p < 16; p++) {
        int idx = p * 128 + tid;
        Ms[idx] = (1.f - mask[b * SS + idx]) * NEG;
    }

    float o[2][8][4];
#pragma unroll
    for (int mi = 0; mi < 2; mi++)
#pragma unroll
        for (int ni = 0; ni < 8; ni++)
#pragma unroll
            for (int t = 0; t < 4; t++) o[mi][ni][t] = 0.f;
    float mst[2][2] = {{-1e30f, -1e30f}, {-1e30f, -1e30f}};
    float lst[2][2] = {{0.f, 0.f}, {0.f, 0.f}};

    const int jt_max = 2 * qt + 1;
    const int rowbase = q0 + wm;
    const int src0 = (lane & ~3) | (cq >> 1);
    const int src1 = src0 + 2;
    const bool oddl = cq & 1;

    for (int jt = 0; jt <= jt_max; jt++) {
        CP_WAIT(0);          // stage jt resident (prefetched a full tile ago)
        __syncthreads();     // + readers of the other stage (tile jt-1) done

        if (jt < jt_max) { issue_kv(jt + 1); CP_COMMIT(); }

        const uint32_t* Ku = (const uint32_t*)(KV + (jt & 1) * KVSTG);
        const uint32_t* Vu = Ku + 64 * SA;
        const float* madd = Ms + jt * 64;

        // register-cache the 16 mask values this thread needs (cols shared
        // by both m-tiles and both row-halves)
        float2 m2[8];
#pragma unroll
        for (int ni = 0; ni < 8; ni++)
            m2[ni] = *(const float2*)&madd[8 * ni + 2 * cq];

        // ---- S = Q @ K^T  (both m-tiles share each K B-fragment)
        float s[2][8][4];
#pragma unroll
        for (int mi = 0; mi < 2; mi++)
#pragma unroll
            for (int ni = 0; ni < 8; ni++)
#pragma unroll
                for (int t = 0; t < 4; t++) s[mi][ni][t] = 0.f;
#pragma unroll
        for (int ks = 0; ks < 8; ks++) {
            const int k = ks * 8;
            uint32_t a0[2], a1[2], a2[2], a3[2];
#pragma unroll
            for (int mi = 0; mi < 2; mi++) {
                int mb = wm + mi * 16;
                a0[mi] = Qu[(mb + r) * SA + k + cq];
                a1[mi] = Qu[(mb + r + 8) * SA + k + cq];
                a2[mi] = Qu[(mb + r) * SA + k + cq + 4];
                a3[mi] = Qu[(mb + r + 8) * SA + k + cq + 4];
            }
#pragma unroll
            for (int ni = 0; ni < 8; ni++) {
                uint32_t b0 = Ku[(8 * ni + r) * SA + k + cq];
                uint32_t b1 = Ku[(8 * ni + r) * SA + k + cq + 4];
                mma_tf32(s[0][ni], a0[0], a1[0], a2[0], a3[0], b0, b1);
                mma_tf32(s[1][ni], a0[1], a1[1], a2[1], a3[1], b0, b1);
            }
        }

        // ---- scale + causal + padding mask (warp-uniform fast path)
        const bool part = (jt * 64 + 63 > rowbase);
        if (!part) {
#pragma unroll
            for (int mi = 0; mi < 2; mi++)
#pragma unroll
                for (int ni = 0; ni < 8; ni++) {
                    s[mi][ni][0] = s[mi][ni][0] * 0.125f + m2[ni].x;
                    s[mi][ni][1] = s[mi][ni][1] * 0.125f + m2[ni].y;
                    s[mi][ni][2] = s[mi][ni][2] * 0.125f + m2[ni].x;
                    s[mi][ni][3] = s[mi][ni][3] * 0.125f + m2[ni].y;
                }
        } else {
            const int colb = jt * 64;
#pragma unroll
            for (int mi = 0; mi < 2; mi++) {
#pragma unroll
                for (int ni = 0; ni < 8; ni++) {
#pragma unroll
                    for (int t = 0; t < 4; t++) {
                        int col = 8 * ni + 2 * cq + (t & 1);
                        int rowg = rowbase + mi * 16 + r + ((t < 2) ? 0 : 8);
                        float mv = (t & 1) ? m2[ni].y : m2[ni].x;
                        float v;
                        if (colb + col > rowg) v = NEG + mv;
                        else                   v = s[mi][ni][t] * 0.125f + mv;
                        s[mi][ni][t] = v;
                    }
                }
            }
        }

        // ---- online softmax
#pragma unroll
        for (int mi = 0; mi < 2; mi++) {
            float mx0 = -1e30f, mx1 = -1e30f;
#pragma unroll
            for (int ni = 0; ni < 8; ni++) {
                mx0 = fmaxf(mx0, fmaxf(s[mi][ni][0], s[mi][ni][1]));
                mx1 = fmaxf(mx1, fmaxf(s[mi][ni][2], s[mi][ni][3]));
            }
            mx0 = fmaxf(mx0, __shfl_xor_sync(0xffffffff, mx0, 1));
            mx0 = fmaxf(mx0, __shfl_xor_sync(0xffffffff, mx0, 2));
            mx1 = fmaxf(mx1, __shfl_xor_sync(0xffffffff, mx1, 1));
            mx1 = fmaxf(mx1, __shfl_xor_sync(0xffffffff, mx1, 2));

            float nm0 = fmaxf(mst[mi][0], mx0), nm1 = fmaxf(mst[mi][1], mx1);
            float sc0 = __expf(mst[mi][0] - nm0), sc1 = __expf(mst[mi][1] - nm1);
            float sum0 = 0.f, sum1 = 0.f;
#pragma unroll
            for (int ni = 0; ni < 8; ni++) {
                s[mi][ni][0] = __expf(s[mi][ni][0] - nm0);
                s[mi][ni][1] = __expf(s[mi][ni][1] - nm0);
                s[mi][ni][2] = __expf(s[mi][ni][2] - nm1);
                s[mi][ni][3] = __expf(s[mi][ni][3] - nm1);
                sum0 += s[mi][ni][0] + s[mi][ni][1];
                sum1 += s[mi][ni][2] + s[mi][ni][3];
            }
            sum0 += __shfl_xor_sync(0xffffffff, sum0, 1);
            sum0 += __shfl_xor_sync(0xffffffff, sum0, 2);
            sum1 += __shfl_xor_sync(0xffffffff, sum1, 1);
            sum1 += __shfl_xor_sync(0xffffffff, sum1, 2);

            lst[mi][0] = lst[mi][0] * sc0 + sum0;  mst[mi][0] = nm0;
            lst[mi][1] = lst[mi][1] * sc1 + sum1;  mst[mi][1] = nm1;

#pragma unroll
            for (int ni = 0; ni < 8; ni++) {
                o[mi][ni][0] *= sc0; o[mi][ni][1] *= sc0;
                o[mi][ni][2] *= sc1; o[mi][ni][3] *= sc1;
            }
        }

        // ---- O += P @ V : shuffle C->A fragment conversion; V shared by mi
#pragma unroll
        for (int ks = 0; ks < 8; ks++) {
            uint32_t pa0[2], pa1[2], pa2[2], pa3[2];
#pragma unroll
            for (int mi = 0; mi < 2; mi++) {
                uint32_t q0r = f2tf32(s[mi][ks][0]), q1r = f2tf32(s[mi][ks][1]);
                uint32_t q2r = f2tf32(s[mi][ks][2]), q3r = f2tf32(s[mi][ks][3]);
                uint32_t x00 = __shfl_sync(0xffffffff, q0r, src0);
                uint32_t x01 = __shfl_sync(0xffffffff, q1r, src0);
                uint32_t x10 = __shfl_sync(0xffffffff, q2r, src0);
                uint32_t x11 = __shfl_sync(0xffffffff, q3r, src0);
                uint32_t x20 = __shfl_sync(0xffffffff, q0r, src1);
                uint32_t x21 = __shfl_sync(0xffffffff, q1r, src1);
                uint32_t x30 = __shfl_sync(0xffffffff, q2r, src1);
                uint32_t x31 = __shfl_sync(0xffffffff, q3r, src1);
                pa0[mi] = oddl ? x01 : x00;
                pa1[mi] = oddl ? x11 : x10;
                pa2[mi] = oddl ? x21 : x20;
                pa3[mi] = oddl ? x31 : x30;
            }
            const int k = ks * 8;
#pragma unroll
            for (int ni = 0; ni < 8; ni++) {
                uint32_t b0 = Vu[(k + cq) * SA + 8 * ni + r];
                uint32_t b1 = Vu[(k + cq + 4) * SA + 8 * ni + r];
                mma_tf32(o[0][ni], pa0[0], pa1[0], pa2[0], pa3[0], b0, b1);
                mma_tf32(o[1][ni], pa0[1], pa1[1], pa2[1], pa3[1], b0, b1);
            }
        }
    }

    // ---- epilogue
#pragma unroll
    for (int mi = 0; mi < 2; mi++) {
        float inv0 = 1.f / lst[mi][0], inv1 = 1.f / lst[mi][1];
        int rw0 = rowbase + mi * 16 + r;
        float* ob0 = g_att + (size_t)(b * SS + rw0) * DD + h * HD;
        float* ob1 = g_att + (size_t)(b * SS + rw0 + 8) * DD + h * HD;
#pragma unroll
        for (int ni = 0; ni < 8; ni++) {
            int col = 8 * ni + 2 * cq;
            float2 w0, w1;
            w0.x = f2tf32f(o[mi][ni][0] * inv0); w0.y = f2tf32f(o[mi][ni][1] * inv0);
            w1.x = f2tf32f(o[mi][ni][2] * inv1); w1.y = f2tf32f(o[mi][ni][3] * inv1);
            *(float2*)(ob0 + col) = w0;
            *(float2*)(ob1 + col) = w1;
        }
    }
}

// ---------------------------------------------------------------------------
extern "C" void kernel_launch(void* const* d_in, const int* in_sizes, int n_in,
                              void* d_out, int out_size)
{
    const float* x    = (const float*)d_in[0];
    const float* mask = (const float*)d_in[1];
    const float* Wq   = (const float*)d_in[2];
    const float* bq   = (const float*)d_in[3];
    const float* Wk   = (const float*)d_in[4];
    const float* bk   = (const float*)d_in[5];
    const float* Wv   = (const float*)d_in[6];
    const float* bv   = (const float*)d_in[7];
    const float* Wo   = (const float*)d_in[8];
    const float* bo   = (const float*)d_in[9];
    float* out = (float*)d_out;

    const int cvt_total = X4 + 4 * W4;
    cvt_all<<<(cvt_total + 255) / 256, 256>>>(x, Wq, Wk, Wv, Wo);

    const int gemm_smem = 3 * (ASZ + BSZ) * sizeof(float);                 // ~107.5 KB
    const int attn_smem = (QR * SA + 2 * KVSTG + SS) * sizeof(float);      // ~110 KB
    cudaFuncSetAttribute(qkv_mma,   cudaFuncAttributeMaxDynamicSharedMemorySize, gemm_smem);
    cudaFuncSetAttribute(oproj_mma, cudaFuncAttributeMaxDynamicSharedMemorySize, gemm_smem);
    cudaFuncSetAttribute(attn_mma,  cudaFuncAttributeMaxDynamicSharedMemorySize, attn_smem);

    dim3 gq(DD / 128, (BB * SS) / 128, 3);
    qkv_mma<<<gq, 128, gemm_smem>>>(bq, bk, bv);

    dim3 ga(SS / QR, HH, BB);
    attn_mma<<<ga, 128, attn_smem>>>(mask);

    dim3 go(DD / 128, (BB * SS) / 128);
    oproj_mma<<<go, 128, gemm_smem>>>(bo, out);
}